// round 13
// baseline (speedup 1.0000x reference)
#include <cuda_runtime.h>
#include <math.h>

// ---------------------------------------------------------------------------
// SubgraphAttention — see prior rounds. All math fp32; GEMMs use packed
// fma.rn.f32x2 (bit-exact IEEE fp32).
// R13: duplicated-B smem layout in gemm_C/gemm_T — B stored as broadcast
// pairs {b,b} (u64), inner loop reads them with LDS.128 directly as fma2
// operands. Removes all 8 bcast2 MOVs (+ SASS expansion + dependency hop)
// per k-step. R12 evidence: register pipelining neutral => issue mix, not
// scheduling, is the cost.
// ---------------------------------------------------------------------------

#define BB 32
#define NN 65
#define SS 64
#define DD 512
#define MROWS (BB * NN)   // 2080

static const size_t OUT_ELEMS  = (size_t)BB * SS * NN * DD;    // 68,157,440
static const size_t LEADER_OFF = OUT_ELEMS;
static const size_t MEMBER_OFF = OUT_ELEMS + (size_t)BB * SS;

// gemm_T dynamic smem: As[2][32][130] floats, then Bdup[2][32][64] u64
#define TT_APAD 130
static const int GT_SMEM = (2 * 32 * TT_APAD) * 4 + (2 * 32 * 64) * 8;  // 66,048
// gemm_C dynamic smem: As[2][32][68] floats, then Bdup[2][32][64] u64
#define TC_APAD 68
static const int GC_SMEM = (2 * 32 * TC_APAD) * 4 + (2 * 32 * 64) * 8;  // 50,176

// ----------------------------- device scratch ------------------------------
__device__ float g_C[DD * DD];
__device__ float g_T[MROWS * DD];
__device__ float g_v1[DD];
__device__ float g_v2[DD];
__device__ float g_s0;
__device__ float g_u1[MROWS];
__device__ float g_u2[MROWS];
__device__ unsigned long long g_rawmask[BB * SS];
__device__ unsigned long long g_mmask[BB * SS];

// ----------------------------- f32x2 helpers -------------------------------
__device__ __forceinline__ void fma2(unsigned long long& d, unsigned long long a,
                                     unsigned long long b) {
    asm("fma.rn.f32x2 %0, %1, %2, %0;" : "+l"(d) : "l"(a), "l"(b));
}
__device__ __forceinline__ unsigned long long bcast2(float x) {
    unsigned long long r;
    asm("mov.b64 %0, {%1, %1};" : "=l"(r) : "f"(x));
    return r;
}
__device__ __forceinline__ float2 unpk2(unsigned long long v) {
    float2 r;
    asm("mov.b64 {%0, %1}, %2;" : "=f"(r.x), "=f"(r.y) : "l"(v));
    return r;
}

// ----------------------------------------------------------------------------
// prep: v1 = Wq^T bk ; v2 = Wk^T bq ; s0 = bq.bk   (16 blocks)
// ----------------------------------------------------------------------------
__global__ __launch_bounds__(256) void prep_kernel(const float* __restrict__ Wq,
                                                   const float* __restrict__ bq,
                                                   const float* __restrict__ Wk,
                                                   const float* __restrict__ bk) {
    __shared__ float sb[512];
    __shared__ float part[4][64];
    __shared__ float red[256];
    const int tid = threadIdx.x;
    const int mat = blockIdx.x >> 3;
    const int c0 = (blockIdx.x & 7) * 64;
    const float* W = mat ? Wk : Wq;
    const float* bv = mat ? bq : bk;

    sb[tid] = bv[tid];
    sb[tid + 256] = bv[tid + 256];
    __syncthreads();

    const int c = c0 + (tid & 63);
    const int q = tid >> 6;
    const int n0 = q * 128;
    float acc = 0.f;
#pragma unroll 8
    for (int n = 0; n < 128; n++) {
        acc += W[(n0 + n) * 512 + c] * sb[n0 + n];
    }
    part[q][tid & 63] = acc;
    __syncthreads();
    if (tid < 64) {
        float v = ((part[0][tid] + part[1][tid]) + part[2][tid]) + part[3][tid];
        (mat ? g_v2 : g_v1)[c0 + tid] = v;
    }

    if (blockIdx.x == 0) {
        red[tid] = bq[tid] * bk[tid] + bq[tid + 256] * bk[tid + 256];
        __syncthreads();
        for (int s = 128; s > 0; s >>= 1) {
            if (tid < s) red[tid] += red[tid + s];
            __syncthreads();
        }
        if (tid == 0) g_s0 = red[0];
    }
}

// ----------------------------------------------------------------------------
// u_kernel: u1[m] = nve[m,:].v1 ; u2[m] = nve[m,:].v2   (one warp per row)
// ----------------------------------------------------------------------------
__global__ __launch_bounds__(256) void u_kernel(const float* __restrict__ nve) {
    __shared__ float sv1[512], sv2[512];
    const int tid = threadIdx.x;
    for (int i = tid; i < 512; i += 256) {
        sv1[i] = g_v1[i];
        sv2[i] = g_v2[i];
    }
    __syncthreads();
    const int w = tid >> 5, lane = tid & 31;
    const int m = blockIdx.x * 8 + w;
    if (m < MROWS) {
        const float* row = nve + (size_t)m * 512;
        float p1 = 0.f, p2 = 0.f;
#pragma unroll
        for (int r = 0; r < 16; r++) {
            float x = row[r * 32 + lane];
            p1 += x * sv1[r * 32 + lane];
            p2 += x * sv2[r * 32 + lane];
        }
        for (int o = 16; o; o >>= 1) {
            p1 += __shfl_xor_sync(0xffffffffu, p1, o);
            p2 += __shfl_xor_sync(0xffffffffu, p2, o);
        }
        if (lane == 0) { g_u1[m] = p1; g_u2[m] = p2; }
    }
}

// ----------------------------------------------------------------------------
// gemm_C: C[m,n] = sum_k Wq[k,m] * Wk[k,n]  (TN, 512x512x512)
// BM=BN=64, BK=32, 128 thr, grid (8,8). Thread tile 4Mx8N.
// DYNAMIC smem: As floats + duplicated-B u64 pairs.
// ----------------------------------------------------------------------------
__global__ __launch_bounds__(128) void gemm_C_kernel(const float* __restrict__ Wq,
                                                     const float* __restrict__ Wk) {
    extern __shared__ __align__(16) float dsmC[];
    float* Asf = dsmC;                                   // [2][32][68]
    unsigned long long* Bsd =
        reinterpret_cast<unsigned long long*>(dsmC + 2 * 32 * TC_APAD);  // [2][32][64]
#define AS_C(buf, k, m) Asf[((buf) * 32 + (k)) * TC_APAD + (m)]
#define BS_C(buf, k, j) Bsd[((buf) * 32 + (k)) * 64 + (j)]

    const int tid = threadIdx.x;
    const int tm = tid & 15;
    const int tn = tid >> 4;
    const int bm0 = blockIdx.x * 64;
    const int bn0 = blockIdx.y * 64;

    unsigned long long acc[16];
#pragma unroll
    for (int i = 0; i < 16; i++) acc[i] = 0ull;

    float4 ra[4], rb[4];
#pragma unroll
    for (int it = 0; it < 4; it++) {
        int idx = tid + it * 128;
        int r = idx >> 4, c4 = (idx & 15) * 4;
        ra[it] = *reinterpret_cast<const float4*>(&Wq[r * 512 + bm0 + c4]);
        rb[it] = *reinterpret_cast<const float4*>(&Wk[r * 512 + bn0 + c4]);
    }
#pragma unroll
    for (int it = 0; it < 4; it++) {
        int idx = tid + it * 128;
        int r = idx >> 4, c4 = (idx & 15) * 4;
        *reinterpret_cast<float4*>(&AS_C(0, r, c4)) = ra[it];
        BS_C(0, r, c4 + 0) = bcast2(rb[it].x);
        BS_C(0, r, c4 + 1) = bcast2(rb[it].y);
        BS_C(0, r, c4 + 2) = bcast2(rb[it].z);
        BS_C(0, r, c4 + 3) = bcast2(rb[it].w);
    }
    __syncthreads();

    for (int kt = 0; kt < 16; kt++) {
        const int cur = kt & 1, nxt = cur ^ 1;
        if (kt < 15) {
            int k0 = (kt + 1) * 32;
#pragma unroll
            for (int it = 0; it < 4; it++) {
                int idx = tid + it * 128;
                int r = idx >> 4, c4 = (idx & 15) * 4;
                ra[it] = *reinterpret_cast<const float4*>(&Wq[(k0 + r) * 512 + bm0 + c4]);
                rb[it] = *reinterpret_cast<const float4*>(&Wk[(k0 + r) * 512 + bn0 + c4]);
            }
        }
#pragma unroll
        for (int k = 0; k < 32; k++) {
            unsigned long long a0 = *reinterpret_cast<const unsigned long long*>(&AS_C(cur, k, 2 * tm));
            unsigned long long a1 = *reinterpret_cast<const unsigned long long*>(&AS_C(cur, k, 2 * tm + 32));
            ulonglong2 p0 = *reinterpret_cast<const ulonglong2*>(&BS_C(cur, k, 8 * tn + 0));
            ulonglong2 p1 = *reinterpret_cast<const ulonglong2*>(&BS_C(cur, k, 8 * tn + 2));
            ulonglong2 p2 = *reinterpret_cast<const ulonglong2*>(&BS_C(cur, k, 8 * tn + 4));
            ulonglong2 p3 = *reinterpret_cast<const ulonglong2*>(&BS_C(cur, k, 8 * tn + 6));
            fma2(acc[0], a0, p0.x); fma2(acc[1], a0, p0.y);
            fma2(acc[2], a0, p1.x); fma2(acc[3], a0, p1.y);
            fma2(acc[4], a0, p2.x); fma2(acc[5], a0, p2.y);
            fma2(acc[6], a0, p3.x); fma2(acc[7], a0, p3.y);
            fma2(acc[8],  a1, p0.x); fma2(acc[9],  a1, p0.y);
            fma2(acc[10], a1, p1.x); fma2(acc[11], a1, p1.y);
            fma2(acc[12], a1, p2.x); fma2(acc[13], a1, p2.y);
            fma2(acc[14], a1, p3.x); fma2(acc[15], a1, p3.y);
        }
        if (kt < 15) {
#pragma unroll
            for (int it = 0; it < 4; it++) {
                int idx = tid + it * 128;
                int r = idx >> 4, c4 = (idx & 15) * 4;
                *reinterpret_cast<float4*>(&AS_C(nxt, r, c4)) = ra[it];
                BS_C(nxt, r, c4 + 0) = bcast2(rb[it].x);
                BS_C(nxt, r, c4 + 1) = bcast2(rb[it].y);
                BS_C(nxt, r, c4 + 2) = bcast2(rb[it].z);
                BS_C(nxt, r, c4 + 3) = bcast2(rb[it].w);
            }
            __syncthreads();
        }
    }
#pragma unroll
    for (int p = 0; p < 2; p++) {
#pragma unroll
        for (int n = 0; n < 8; n++) {
            float2 v = unpk2(acc[p * 8 + n]);
            int m = bm0 + 2 * tm + 32 * p;
            int nc = bn0 + 8 * tn + n;
            g_C[m * 512 + nc] = v.x;
            g_C[(m + 1) * 512 + nc] = v.y;
        }
    }
#undef AS_C
#undef BS_C
}

// ----------------------------------------------------------------------------
// gemm_T: T[m,n] = sum_k nve[m,k] * C[k,n]  (NN, 2080x512x512)
// BM=128, BN=64, BK=32, 128 thr, grid (17,8)=136. Thread tile 8Mx8N.
// DYNAMIC smem: As transposed [2][32][130] floats + duplicated-B u64 pairs.
// ----------------------------------------------------------------------------
__global__ __launch_bounds__(128) void gemm_T_kernel(const float* __restrict__ nve) {
    extern __shared__ __align__(16) float dsm[];
    float* Asf = dsm;                                    // [2][32][130]
    unsigned long long* Bsd =
        reinterpret_cast<unsigned long long*>(dsm + 2 * 32 * TT_APAD);  // [2][32][64]
#define AS_T(buf, k, m) Asf[((buf) * 32 + (k)) * TT_APAD + (m)]
#define BS_T(buf, k, j) Bsd[((buf) * 32 + (k)) * 64 + (j)]

    const int tid = threadIdx.x;
    const int tm = tid & 15;
    const int tn = tid >> 4;
    const int m0 = blockIdx.x * 128;
    const int n0 = blockIdx.y * 64;

    unsigned long long acc[32];
#pragma unroll
    for (int i = 0; i < 32; i++) acc[i] = 0ull;

    const float4 z4 = make_float4(0.f, 0.f, 0.f, 0.f);
    float4 ra[8], rb[4];
#pragma unroll
    for (int it = 0; it < 8; it++) {
        int idx = tid + it * 128;
        int m = m0 + (idx >> 3), k4 = (idx & 7) * 4;
        ra[it] = (m < MROWS) ? *reinterpret_cast<const float4*>(&nve[m * 512 + k4]) : z4;
    }
#pragma unroll
    for (int it = 0; it < 4; it++) {
        int idx = tid + it * 128;
        int r = idx >> 4, c4 = (idx & 15) * 4;
        rb[it] = *reinterpret_cast<const float4*>(&g_C[r * 512 + n0 + c4]);
    }
#pragma unroll
    for (int it = 0; it < 8; it++) {
        int idx = tid + it * 128;
        int ml = idx >> 3, k4 = (idx & 7) * 4;
        AS_T(0, k4 + 0, ml) = ra[it].x;
        AS_T(0, k4 + 1, ml) = ra[it].y;
        AS_T(0, k4 + 2, ml) = ra[it].z;
        AS_T(0, k4 + 3, ml) = ra[it].w;
    }
#pragma unroll
    for (int it = 0; it < 4; it++) {
        int idx = tid + it * 128;
        int r = idx >> 4, c4 = (idx & 15) * 4;
        BS_T(0, r, c4 + 0) = bcast2(rb[it].x);
        BS_T(0, r, c4 + 1) = bcast2(rb[it].y);
        BS_T(0, r, c4 + 2) = bcast2(rb[it].z);
        BS_T(0, r, c4 + 3) = bcast2(rb[it].w);
    }
    __syncthreads();

    for (int kt = 0; kt < 16; kt++) {
        const int cur = kt & 1, nxt = cur ^ 1;
        if (kt < 15) {
            int k0 = (kt + 1) * 32;
#pragma unroll
            for (int it = 0; it < 8; it++) {
                int idx = tid + it * 128;
                int m = m0 + (idx >> 3), k4 = (idx & 7) * 4;
                ra[it] = (m < MROWS)
                             ? *reinterpret_cast<const float4*>(&nve[m * 512 + k0 + k4])
                             : z4;
            }
#pragma unroll
            for (int it = 0; it < 4; it++) {
                int idx = tid + it * 128;
                int r = idx >> 4, c4 = (idx & 15) * 4;
                rb[it] = *reinterpret_cast<const float4*>(&g_C[(k0 + r) * 512 + n0 + c4]);
            }
        }
#pragma unroll
        for (int k = 0; k < 32; k++) {
            unsigned long long a[4];
#pragma unroll
            for (int p = 0; p < 4; p++)
                a[p] = *reinterpret_cast<const unsigned long long*>(&AS_T(cur, k, 2 * tm + 32 * p));
            ulonglong2 p0 = *reinterpret_cast<const ulonglong2*>(&BS_T(cur, k, 8 * tn + 0));
            ulonglong2 p1 = *reinterpret_cast<const ulonglong2*>(&BS_T(cur, k, 8 * tn + 2));
            ulonglong2 p2 = *reinterpret_cast<const ulonglong2*>(&BS_T(cur, k, 8 * tn + 4));
            ulonglong2 p3 = *reinterpret_cast<const ulonglong2*>(&BS_T(cur, k, 8 * tn + 6));
#pragma unroll
            for (int p = 0; p < 4; p++) {
                fma2(acc[p * 8 + 0], a[p], p0.x);
                fma2(acc[p * 8 + 1], a[p], p0.y);
                fma2(acc[p * 8 + 2], a[p], p1.x);
                fma2(acc[p * 8 + 3], a[p], p1.y);
                fma2(acc[p * 8 + 4], a[p], p2.x);
                fma2(acc[p * 8 + 5], a[p], p2.y);
                fma2(acc[p * 8 + 6], a[p], p3.x);
                fma2(acc[p * 8 + 7], a[p], p3.y);
            }
        }
        if (kt < 15) {
#pragma unroll
            for (int it = 0; it < 8; it++) {
                int idx = tid + it * 128;
                int ml = idx >> 3, k4 = (idx & 7) * 4;
                AS_T(nxt, k4 + 0, ml) = ra[it].x;
                AS_T(nxt, k4 + 1, ml) = ra[it].y;
                AS_T(nxt, k4 + 2, ml) = ra[it].z;
                AS_T(nxt, k4 + 3, ml) = ra[it].w;
            }
#pragma unroll
            for (int it = 0; it < 4; it++) {
                int idx = tid + it * 128;
                int r = idx >> 4, c4 = (idx & 15) * 4;
                BS_T(nxt, r, c4 + 0) = bcast2(rb[it].x);
                BS_T(nxt, r, c4 + 1) = bcast2(rb[it].y);
                BS_T(nxt, r, c4 + 2) = bcast2(rb[it].z);
                BS_T(nxt, r, c4 + 3) = bcast2(rb[it].w);
            }
            __syncthreads();
        }
    }
#pragma unroll
    for (int p = 0; p < 4; p++) {
#pragma unroll
        for (int n = 0; n < 8; n++) {
            float2 v = unpk2(acc[p * 8 + n]);
            int m = m0 + 2 * tm + 32 * p;
            int nc = n0 + 8 * tn + n;
            if (m < MROWS) g_T[m * 512 + nc] = v.x;
            if (m + 1 < MROWS) g_T[(m + 1) * 512 + nc] = v.y;
        }
    }
#undef AS_T
#undef BS_T
}

// ----------------------------------------------------------------------------
// score_kernel: S[i,j] = T[b,i,:].nve[b,j,:] for 16 i-rows, j in [0,65);
// softmax + threshold -> raw masks. Grid (4, BB) = 128 blocks.
// ----------------------------------------------------------------------------
__global__ __launch_bounds__(256) void score_kernel(const float* __restrict__ nve) {
    __shared__ __align__(16) float As[2][16][18];
    __shared__ __align__(16) float Bs[2][16][68];
    __shared__ float sS[16][68];
    __shared__ float su1[16];
    __shared__ float su2[65];

    const int b = blockIdx.y;
    const int i0 = 1 + 16 * blockIdx.x;
    const int tid = threadIdx.x;
    const int tm = tid & 7;
    const int tn = tid >> 3;

    if (tid < 16) su1[tid] = g_u1[b * 65 + i0 + tid];
    else if (tid < 16 + 65) su2[tid - 16] = g_u2[b * 65 + (tid - 16)];

    const float* Tb = g_T + ((size_t)b * 65 + i0) * 512;
    const float* Nb = nve + (size_t)b * 65 * 512;

    unsigned long long acc[2] = {0ull, 0ull};
    unsigned long long acc64 = 0ull;

    const int arow = tid >> 2, ak4 = (tid & 3) * 4;
    const int brow1 = (tid + 256) >> 2, bk41 = ((tid + 256) & 3) * 4;
    const bool hasB1 = (tid + 256) < 260;
    float4 ra4, rb4[2];
    {
        if (tid < 64) ra4 = *reinterpret_cast<const float4*>(&Tb[arow * 512 + ak4]);
        rb4[0] = *reinterpret_cast<const float4*>(&Nb[arow * 512 + ak4]);
        if (hasB1) rb4[1] = *reinterpret_cast<const float4*>(&Nb[brow1 * 512 + bk41]);
        if (tid < 64) {
            As[0][ak4 + 0][arow] = ra4.x;
            As[0][ak4 + 1][arow] = ra4.y;
            As[0][ak4 + 2][arow] = ra4.z;
            As[0][ak4 + 3][arow] = ra4.w;
        }
        Bs[0][ak4 + 0][arow] = rb4[0].x;
        Bs[0][ak4 + 1][arow] = rb4[0].y;
        Bs[0][ak4 + 2][arow] = rb4[0].z;
        Bs[0][ak4 + 3][arow] = rb4[0].w;
        if (hasB1) {
            Bs[0][bk41 + 0][brow1] = rb4[1].x;
            Bs[0][bk41 + 1][brow1] = rb4[1].y;
            Bs[0][bk41 + 2][brow1] = rb4[1].z;
            Bs[0][bk41 + 3][brow1] = rb4[1].w;
        }
    }
    __syncthreads();

    for (int kt = 0; kt < 32; kt++) {
        const int cur = kt & 1, nxt = cur ^ 1;
        if (kt < 31) {
            int k0 = (kt + 1) * 16;
            if (tid < 64) ra4 = *reinterpret_cast<const float4*>(&Tb[arow * 512 + k0 + ak4]);
            rb4[0] = *reinterpret_cast<const float4*>(&Nb[arow * 512 + k0 + ak4]);
            if (hasB1) rb4[1] = *reinterpret_cast<const float4*>(&Nb[brow1 * 512 + k0 + bk41]);
        }
#pragma unroll
        for (int k = 0; k < 16; k++) {
            unsigned long long a = *reinterpret_cast<const unsigned long long*>(&As[cur][k][2 * tm]);
            float2 bv = *reinterpret_cast<const float2*>(&Bs[cur][k][2 * tn]);
            fma2(acc[0], a, bcast2(bv.x));
            fma2(acc[1], a, bcast2(bv.y));
            if (tn == 0) fma2(acc64, a, bcast2(Bs[cur][k][64]));
        }
        if (kt < 31) {
            if (tid < 64) {
                As[nxt][ak4 + 0][arow] = ra4.x;
                As[nxt][ak4 + 1][arow] = ra4.y;
                As[nxt][ak4 + 2][arow] = ra4.z;
                As[nxt][ak4 + 3][arow] = ra4.w;
            }
            Bs[nxt][ak4 + 0][arow] = rb4[0].x;
            Bs[nxt][ak4 + 1][arow] = rb4[0].y;
            Bs[nxt][ak4 + 2][arow] = rb4[0].z;
            Bs[nxt][ak4 + 3][arow] = rb4[0].w;
            if (hasB1) {
                Bs[nxt][bk41 + 0][brow1] = rb4[1].x;
                Bs[nxt][bk41 + 1][brow1] = rb4[1].y;
                Bs[nxt][bk41 + 2][brow1] = rb4[1].z;
                Bs[nxt][bk41 + 3][brow1] = rb4[1].w;
            }
            __syncthreads();
        }
    }

#pragma unroll
    for (int q = 0; q < 2; q++) {
        float2 v = unpk2(acc[q]);
        sS[2 * tm][2 * tn + q] = v.x;
        sS[2 * tm + 1][2 * tn + q] = v.y;
    }
    if (tn == 0) {
        float2 v = unpk2(acc64);
        sS[2 * tm][64] = v.x;
        sS[2 * tm + 1][64] = v.y;
    }
    __syncthreads();

    const int w = tid >> 5, lane = tid & 31;
    const unsigned FULL = 0xffffffffu;
    const float INV_SQRTD = 0.044194173824159216f;
    const float s0 = g_s0;
#pragma unroll
    for (int rr = 0; rr < 2; rr++) {
        int r = w * 2 + rr;
        int i = i0 + r;
        float base = su1[r] + s0;
        int j1 = 32 + lane;
        float L0 = (lane == i) ? 0.f : (sS[r][lane] + base + su2[lane]) * INV_SQRTD;
        float L1 = (j1 == i) ? 0.f : (sS[r][j1] + base + su2[j1]) * INV_SQRTD;
        float L2 = (lane == 0)
                       ? ((i == 64) ? 0.f : (sS[r][64] + base + su2[64]) * INV_SQRTD)
                       : -1e30f;
        float mx = fmaxf(L0, fmaxf(L1, L2));
        for (int o = 16; o; o >>= 1) mx = fmaxf(mx, __shfl_xor_sync(FULL, mx, o));
        float e0 = expf(L0 - mx);
        float e1 = expf(L1 - mx);
        float e2 = (lane == 0) ? expf(L2 - mx) : 0.f;
        float sm = e0 + e1 + e2;
        for (int o = 16; o; o >>= 1) sm += __shfl_xor_sync(FULL, sm, o);
        float inv = 1.0f / sm;
        unsigned bal0 = __ballot_sync(FULL, (lane >= 1) && (e0 * inv > 0.05f));
        unsigned bal1 = __ballot_sync(FULL, e1 * inv > 0.05f);
        unsigned bal2 = __ballot_sync(FULL, (lane == 0) && (e2 * inv > 0.05f));
        if (lane == 0) {
            unsigned long long m = ((unsigned long long)(bal0 >> 1)) |
                                   ((unsigned long long)bal1 << 31) |
                                   ((unsigned long long)(bal2 & 1u) << 63);
            m |= 1ull << (i - 1);
            g_rawmask[b * 64 + (i - 1)] = m;
        }
    }
}

// ----------------------------------------------------------------------------
// cluster: greedy sequential clustering per batch + leader/member outputs
// ----------------------------------------------------------------------------
__global__ __launch_bounds__(256) void cluster_kernel(float* __restrict__ out) {
    __shared__ unsigned long long sm[64];
    __shared__ unsigned long long sf[64];
    __shared__ unsigned long long sl;
    const int b = blockIdx.x;
    const int tid = threadIdx.x;
    if (tid < 64) sm[tid] = g_rawmask[b * 64 + tid];
    __syncthreads();
    if (tid == 0) {
        unsigned long long used = 0ull, lead = 0ull;
        for (int i = 0; i < 64; i++) {
            unsigned long long m = sm[i];
            if (!((used >> i) & 1ull)) {
                lead |= 1ull << i;
                used |= m;
                sf[i] = m;
            } else {
                sf[i] = 0ull;
            }
        }
        sl = lead;
    }
    __syncthreads();
    unsigned long long lead = sl;
    if (tid < 64) {
        out[LEADER_OFF + (size_t)b * 64 + tid] = ((lead >> tid) & 1ull) ? 1.0f : 0.0f;
        g_mmask[b * 64 + tid] = sf[tid];
    }
    for (int idx = tid; idx < 4096; idx += 256) {
        out[MEMBER_OFF + (size_t)b * 4096 + idx] =
            ((sf[idx >> 6] >> (idx & 63)) & 1ull) ? 1.0f : 0.0f;
    }
}

// ----------------------------------------------------------------------------
// expansion: write-bandwidth bound (~273 MB), streaming stores.
// ----------------------------------------------------------------------------
__global__ __launch_bounds__(256) void expand_kernel(const float* __restrict__ nve,
                                                     const float* __restrict__ cls,
                                                     float* __restrict__ out) {
    const int bi = blockIdx.x;
    const int b = bi >> 6;
    const unsigned long long mask = g_mmask[bi];
    const bool lead = (mask != 0ull);

    const float4* nve4 = reinterpret_cast<const float4*>(nve);
    const float4* cls4 = reinterpret_cast<const float4*>(cls);
    float4* out4 = reinterpret_cast<float4*>(out) + (size_t)bi * 65 * 128;

    const int quad = threadIdx.x & 127;
    const int sub = threadIdx.x >> 7;
    const float4 zero4 = make_float4(0.f, 0.f, 0.f, 0.f);

    for (int r = sub; r < 65; r += 2) {
        float4 v;
        if (r == 0) {
            v = lead ? cls4[quad] : zero4;
        } else {
            v = ((mask >> (r - 1)) & 1ull) ? nve4[((size_t)b * 65 + r) * 128 + quad]
                                           : zero4;
        }
        __stcs(&out4[(size_t)r * 128 + quad], v);
    }
}

// ----------------------------------------------------------------------------
extern "C" void kernel_launch(void* const* d_in, const int* in_sizes, int n_in,
                              void* d_out, int out_size) {
    // inputs: desc_embeddings, name_value_embeddings, Wq, bq, Wk, bk, cls
    const float* nve = (const float*)d_in[1];
    const float* Wq  = (const float*)d_in[2];
    const float* bq  = (const float*)d_in[3];
    const float* Wk  = (const float*)d_in[4];
    const float* bk  = (const float*)d_in[5];
    const float* cls = (const float*)d_in[6];
    float* out = (float*)d_out;

    cudaFuncSetAttribute(gemm_T_kernel, cudaFuncAttributeMaxDynamicSharedMemorySize,
                         GT_SMEM);
    cudaFuncSetAttribute(gemm_C_kernel, cudaFuncAttributeMaxDynamicSharedMemorySize,
                         GC_SMEM);

    prep_kernel<<<16, 256>>>(Wq, bq, Wk, bk);
    u_kernel<<<260, 256>>>(nve);
    gemm_C_kernel<<<dim3(8, 8), 128, GC_SMEM>>>(Wq, Wk);
    gemm_T_kernel<<<dim3(17, 8), 128, GT_SMEM>>>(nve);
    score_kernel<<<dim3(4, BB), 256>>>(nve);
    cluster_kernel<<<BB, 256>>>(out);
    expand_kernel<<<BB * SS, 256>>>(nve, cls, out);
}

// round 14
// speedup vs baseline: 1.0931x; 1.0931x over previous
#include <cuda_runtime.h>
#include <math.h>

// ---------------------------------------------------------------------------
// SubgraphAttention — see prior rounds. All math fp32; GEMMs use packed
// fma.rn.f32x2 (bit-exact IEEE fp32).
// R14: revert R13 dup-B (regression; fma2 formulation is at plateau).
// gemm_C (never profiled; budget says ~25-30us at 64 blocks) -> split-K=4,
// grid 256 blocks; reduction fused into gemm_T's B staging (the fusion
// direction R10 proved cheap). score path untouched.
// ---------------------------------------------------------------------------

#define BB 32
#define NN 65
#define SS 64
#define DD 512
#define MROWS (BB * NN)   // 2080

static const size_t OUT_ELEMS  = (size_t)BB * SS * NN * DD;    // 68,157,440
static const size_t LEADER_OFF = OUT_ELEMS;
static const size_t MEMBER_OFF = OUT_ELEMS + (size_t)BB * SS;

// gemm_T dynamic smem layout: As[2][32][130] then Bs[2][32][64]
#define TT_APAD 130
static const int GT_SMEM = (2 * 32 * TT_APAD + 2 * 32 * 64) * 4;  // 49,664 B

// ----------------------------- device scratch ------------------------------
__device__ float g_Cp[4][DD * DD];        // C split-K partials
__device__ float g_T[MROWS * DD];
__device__ float g_v1[DD];
__device__ float g_v2[DD];
__device__ float g_s0;
__device__ float g_u1[MROWS];
__device__ float g_u2[MROWS];
__device__ unsigned long long g_rawmask[BB * SS];
__device__ unsigned long long g_mmask[BB * SS];

// ----------------------------- f32x2 helpers -------------------------------
__device__ __forceinline__ void fma2(unsigned long long& d, unsigned long long a,
                                     unsigned long long b) {
    asm("fma.rn.f32x2 %0, %1, %2, %0;" : "+l"(d) : "l"(a), "l"(b));
}
__device__ __forceinline__ unsigned long long bcast2(float x) {
    unsigned long long r;
    asm("mov.b64 %0, {%1, %1};" : "=l"(r) : "f"(x));
    return r;
}
__device__ __forceinline__ float2 unpk2(unsigned long long v) {
    float2 r;
    asm("mov.b64 {%0, %1}, %2;" : "=f"(r.x), "=f"(r.y) : "l"(v));
    return r;
}

// ----------------------------------------------------------------------------
// prep: v1 = Wq^T bk ; v2 = Wk^T bq ; s0 = bq.bk   (16 blocks)
// ----------------------------------------------------------------------------
__global__ __launch_bounds__(256) void prep_kernel(const float* __restrict__ Wq,
                                                   const float* __restrict__ bq,
                                                   const float* __restrict__ Wk,
                                                   const float* __restrict__ bk) {
    __shared__ float sb[512];
    __shared__ float part[4][64];
    __shared__ float red[256];
    const int tid = threadIdx.x;
    const int mat = blockIdx.x >> 3;
    const int c0 = (blockIdx.x & 7) * 64;
    const float* W = mat ? Wk : Wq;
    const float* bv = mat ? bq : bk;

    sb[tid] = bv[tid];
    sb[tid + 256] = bv[tid + 256];
    __syncthreads();

    const int c = c0 + (tid & 63);
    const int q = tid >> 6;
    const int n0 = q * 128;
    float acc = 0.f;
#pragma unroll 8
    for (int n = 0; n < 128; n++) {
        acc += W[(n0 + n) * 512 + c] * sb[n0 + n];
    }
    part[q][tid & 63] = acc;
    __syncthreads();
    if (tid < 64) {
        float v = ((part[0][tid] + part[1][tid]) + part[2][tid]) + part[3][tid];
        (mat ? g_v2 : g_v1)[c0 + tid] = v;
    }

    if (blockIdx.x == 0) {
        red[tid] = bq[tid] * bk[tid] + bq[tid + 256] * bk[tid + 256];
        __syncthreads();
        for (int s = 128; s > 0; s >>= 1) {
            if (tid < s) red[tid] += red[tid + s];
            __syncthreads();
        }
        if (tid == 0) g_s0 = red[0];
    }
}

// ----------------------------------------------------------------------------
// u_kernel: u1[m] = nve[m,:].v1 ; u2[m] = nve[m,:].v2   (one warp per row)
// ----------------------------------------------------------------------------
__global__ __launch_bounds__(256) void u_kernel(const float* __restrict__ nve) {
    __shared__ float sv1[512], sv2[512];
    const int tid = threadIdx.x;
    for (int i = tid; i < 512; i += 256) {
        sv1[i] = g_v1[i];
        sv2[i] = g_v2[i];
    }
    __syncthreads();
    const int w = tid >> 5, lane = tid & 31;
    const int m = blockIdx.x * 8 + w;
    if (m < MROWS) {
        const float* row = nve + (size_t)m * 512;
        float p1 = 0.f, p2 = 0.f;
#pragma unroll
        for (int r = 0; r < 16; r++) {
            float x = row[r * 32 + lane];
            p1 += x * sv1[r * 32 + lane];
            p2 += x * sv2[r * 32 + lane];
        }
        for (int o = 16; o; o >>= 1) {
            p1 += __shfl_xor_sync(0xffffffffu, p1, o);
            p2 += __shfl_xor_sync(0xffffffffu, p2, o);
        }
        if (lane == 0) { g_u1[m] = p1; g_u2[m] = p2; }
    }
}

// ----------------------------------------------------------------------------
// gemm_C: Cp[z][m,n] = sum_{k in chunk z} Wq[k,m] * Wk[k,n]  (512x512x128)
// Split-K=4. BM=BN=64, BK=32, 128 thr, grid (8,8,4)=256. Tile 4Mx8N.
// ----------------------------------------------------------------------------
__global__ __launch_bounds__(128) void gemm_C_kernel(const float* __restrict__ Wq,
                                                     const float* __restrict__ Wk) {
    __shared__ __align__(16) float As[2][32][68];
    __shared__ __align__(16) float Bs[2][32][64];
    const int tid = threadIdx.x;
    const int tm = tid & 15;
    const int tn = tid >> 4;
    const int bm0 = blockIdx.x * 64;
    const int bn0 = blockIdx.y * 64;
    const int kbase = blockIdx.z * 128;

    unsigned long long acc[16];
#pragma unroll
    for (int i = 0; i < 16; i++) acc[i] = 0ull;

    float4 ra[4], rb[4];
#pragma unroll
    for (int it = 0; it < 4; it++) {
        int idx = tid + it * 128;
        int r = idx >> 4, c4 = (idx & 15) * 4;
        ra[it] = *reinterpret_cast<const float4*>(&Wq[(kbase + r) * 512 + bm0 + c4]);
        rb[it] = *reinterpret_cast<const float4*>(&Wk[(kbase + r) * 512 + bn0 + c4]);
    }
#pragma unroll
    for (int it = 0; it < 4; it++) {
        int idx = tid + it * 128;
        int r = idx >> 4, c4 = (idx & 15) * 4;
        *reinterpret_cast<float4*>(&As[0][r][c4]) = ra[it];
        *reinterpret_cast<float4*>(&Bs[0][r][c4]) = rb[it];
    }
    __syncthreads();

    for (int kt = 0; kt < 4; kt++) {
        const int cur = kt & 1, nxt = cur ^ 1;
        if (kt < 3) {
            int k0 = kbase + (kt + 1) * 32;
#pragma unroll
            for (int it = 0; it < 4; it++) {
                int idx = tid + it * 128;
                int r = idx >> 4, c4 = (idx & 15) * 4;
                ra[it] = *reinterpret_cast<const float4*>(&Wq[(k0 + r) * 512 + bm0 + c4]);
                rb[it] = *reinterpret_cast<const float4*>(&Wk[(k0 + r) * 512 + bn0 + c4]);
            }
        }
#pragma unroll
        for (int k = 0; k < 32; k++) {
            unsigned long long a0 = *reinterpret_cast<const unsigned long long*>(&As[cur][k][2 * tm]);
            unsigned long long a1 = *reinterpret_cast<const unsigned long long*>(&As[cur][k][2 * tm + 32]);
            float4 b0 = *reinterpret_cast<const float4*>(&Bs[cur][k][8 * tn]);
            float4 b1 = *reinterpret_cast<const float4*>(&Bs[cur][k][8 * tn + 4]);
            unsigned long long bb[8] = {bcast2(b0.x), bcast2(b0.y), bcast2(b0.z), bcast2(b0.w),
                                        bcast2(b1.x), bcast2(b1.y), bcast2(b1.z), bcast2(b1.w)};
#pragma unroll
            for (int n = 0; n < 8; n++) {
                fma2(acc[n], a0, bb[n]);
                fma2(acc[8 + n], a1, bb[n]);
            }
        }
        if (kt < 3) {
#pragma unroll
            for (int it = 0; it < 4; it++) {
                int idx = tid + it * 128;
                int r = idx >> 4, c4 = (idx & 15) * 4;
                *reinterpret_cast<float4*>(&As[nxt][r][c4]) = ra[it];
                *reinterpret_cast<float4*>(&Bs[nxt][r][c4]) = rb[it];
            }
            __syncthreads();
        }
    }
    float* dst = g_Cp[blockIdx.z];
#pragma unroll
    for (int p = 0; p < 2; p++) {
#pragma unroll
        for (int n = 0; n < 8; n++) {
            float2 v = unpk2(acc[p * 8 + n]);
            int m = bm0 + 2 * tm + 32 * p;
            int nc = bn0 + 8 * tn + n;
            dst[m * 512 + nc] = v.x;
            dst[(m + 1) * 512 + nc] = v.y;
        }
    }
}

// ----------------------------------------------------------------------------
// gemm_T: T[m,n] = sum_k nve[m,k] * C[k,n], C = Cp0+Cp1+Cp2+Cp3 fused at B
// staging (adds are 1/32 of the loop; R10 measured this fusion cheap).
// BM=128, BN=64, BK=32, 128 thr, grid (17,8)=136. Thread tile 8Mx8N.
// DYNAMIC smem 49,664 B. Inner loop = R11 (best measured).
// ----------------------------------------------------------------------------
__global__ __launch_bounds__(128) void gemm_T_kernel(const float* __restrict__ nve) {
    extern __shared__ __align__(16) float dsm[];
    float* Asf = dsm;                          // [2][32][130]
    float* Bsf = dsm + 2 * 32 * TT_APAD;       // [2][32][64]
#define AS_T(buf, k, m) Asf[((buf) * 32 + (k)) * TT_APAD + (m)]
#define BS_T(buf, k, n) Bsf[((buf) * 32 + (k)) * 64 + (n)]

    const int tid = threadIdx.x;
    const int tm = tid & 15;
    const int tn = tid >> 4;
    const int m0 = blockIdx.x * 128;
    const int n0 = blockIdx.y * 64;
    const float* C0 = g_Cp[0];
    const float* C1 = g_Cp[1];
    const float* C2 = g_Cp[2];
    const float* C3 = g_Cp[3];

    unsigned long long acc[32];
#pragma unroll
    for (int i = 0; i < 32; i++) acc[i] = 0ull;

    const float4 z4 = make_float4(0.f, 0.f, 0.f, 0.f);
    float4 ra[8], rb[4];
#pragma unroll
    for (int it = 0; it < 8; it++) {
        int idx = tid + it * 128;
        int m = m0 + (idx >> 3), k4 = (idx & 7) * 4;
        ra[it] = (m < MROWS) ? *reinterpret_cast<const float4*>(&nve[m * 512 + k4]) : z4;
    }
#pragma unroll
    for (int it = 0; it < 4; it++) {
        int idx = tid + it * 128;
        int r = idx >> 4, c4 = (idx & 15) * 4;
        size_t off = (size_t)r * 512 + n0 + c4;
        float4 v0 = *reinterpret_cast<const float4*>(&C0[off]);
        float4 v1 = *reinterpret_cast<const float4*>(&C1[off]);
        float4 v2 = *reinterpret_cast<const float4*>(&C2[off]);
        float4 v3 = *reinterpret_cast<const float4*>(&C3[off]);
        rb[it] = make_float4((((v0.x + v1.x) + v2.x) + v3.x),
                             (((v0.y + v1.y) + v2.y) + v3.y),
                             (((v0.z + v1.z) + v2.z) + v3.z),
                             (((v0.w + v1.w) + v2.w) + v3.w));
    }
#pragma unroll
    for (int it = 0; it < 8; it++) {
        int idx = tid + it * 128;
        int ml = idx >> 3, k4 = (idx & 7) * 4;
        AS_T(0, k4 + 0, ml) = ra[it].x;
        AS_T(0, k4 + 1, ml) = ra[it].y;
        AS_T(0, k4 + 2, ml) = ra[it].z;
        AS_T(0, k4 + 3, ml) = ra[it].w;
    }
#pragma unroll
    for (int it = 0; it < 4; it++) {
        int idx = tid + it * 128;
        int r = idx >> 4, c4 = (idx & 15) * 4;
        *reinterpret_cast<float4*>(&BS_T(0, r, c4)) = rb[it];
    }
    __syncthreads();

    for (int kt = 0; kt < 16; kt++) {
        const int cur = kt & 1, nxt = cur ^ 1;
        if (kt < 15) {
            int k0 = (kt + 1) * 32;
#pragma unroll
            for (int it = 0; it < 8; it++) {
                int idx = tid + it * 128;
                int m = m0 + (idx >> 3), k4 = (idx & 7) * 4;
                ra[it] = (m < MROWS)
                             ? *reinterpret_cast<const float4*>(&nve[m * 512 + k0 + k4])
                             : z4;
            }
#pragma unroll
            for (int it = 0; it < 4; it++) {
                int idx = tid + it * 128;
                int r = idx >> 4, c4 = (idx & 15) * 4;
                size_t off = (size_t)(k0 + r) * 512 + n0 + c4;
                float4 v0 = *reinterpret_cast<const float4*>(&C0[off]);
                float4 v1 = *reinterpret_cast<const float4*>(&C1[off]);
                float4 v2 = *reinterpret_cast<const float4*>(&C2[off]);
                float4 v3 = *reinterpret_cast<const float4*>(&C3[off]);
                rb[it] = make_float4((((v0.x + v1.x) + v2.x) + v3.x),
                                     (((v0.y + v1.y) + v2.y) + v3.y),
                                     (((v0.z + v1.z) + v2.z) + v3.z),
                                     (((v0.w + v1.w) + v2.w) + v3.w));
            }
        }
#pragma unroll
        for (int k = 0; k < 32; k++) {
            unsigned long long a[4];
#pragma unroll
            for (int p = 0; p < 4; p++)
                a[p] = *reinterpret_cast<const unsigned long long*>(&AS_T(cur, k, 2 * tm + 32 * p));
            float4 b0 = *reinterpret_cast<const float4*>(&BS_T(cur, k, 8 * tn));
            float4 b1 = *reinterpret_cast<const float4*>(&BS_T(cur, k, 8 * tn + 4));
            unsigned long long bb[8] = {bcast2(b0.x), bcast2(b0.y), bcast2(b0.z), bcast2(b0.w),
                                        bcast2(b1.x), bcast2(b1.y), bcast2(b1.z), bcast2(b1.w)};
#pragma unroll
            for (int p = 0; p < 4; p++) {
#pragma unroll
                for (int n = 0; n < 8; n++) fma2(acc[p * 8 + n], a[p], bb[n]);
            }
        }
        if (kt < 15) {
#pragma unroll
            for (int it = 0; it < 8; it++) {
                int idx = tid + it * 128;
                int ml = idx >> 3, k4 = (idx & 7) * 4;
                AS_T(nxt, k4 + 0, ml) = ra[it].x;
                AS_T(nxt, k4 + 1, ml) = ra[it].y;
                AS_T(nxt, k4 + 2, ml) = ra[it].z;
                AS_T(nxt, k4 + 3, ml) = ra[it].w;
            }
#pragma unroll
            for (int it = 0; it < 4; it++) {
                int idx = tid + it * 128;
                int r = idx >> 4, c4 = (idx & 15) * 4;
                *reinterpret_cast<float4*>(&BS_T(nxt, r, c4)) = rb[it];
            }
            __syncthreads();
        }
    }
#pragma unroll
    for (int p = 0; p < 4; p++) {
#pragma unroll
        for (int n = 0; n < 8; n++) {
            float2 v = unpk2(acc[p * 8 + n]);
            int m = m0 + 2 * tm + 32 * p;
            int nc = n0 + 8 * tn + n;
            if (m < MROWS) g_T[m * 512 + nc] = v.x;
            if (m + 1 < MROWS) g_T[(m + 1) * 512 + nc] = v.y;
        }
    }
#undef AS_T
#undef BS_T
}

// ----------------------------------------------------------------------------
// score_kernel: S[i,j] = T[b,i,:].nve[b,j,:] for 16 i-rows, j in [0,65);
// softmax + threshold -> raw masks. Grid (4, BB) = 128 blocks. (R11 version.)
// ----------------------------------------------------------------------------
__global__ __launch_bounds__(256) void score_kernel(const float* __restrict__ nve) {
    __shared__ __align__(16) float As[2][16][18];
    __shared__ __align__(16) float Bs[2][16][68];
    __shared__ float sS[16][68];
    __shared__ float su1[16];
    __shared__ float su2[65];

    const int b = blockIdx.y;
    const int i0 = 1 + 16 * blockIdx.x;
    const int tid = threadIdx.x;
    const int tm = tid & 7;
    const int tn = tid >> 3;

    if (tid < 16) su1[tid] = g_u1[b * 65 + i0 + tid];
    else if (tid < 16 + 65) su2[tid - 16] = g_u2[b * 65 + (tid - 16)];

    const float* Tb = g_T + ((size_t)b * 65 + i0) * 512;
    const float* Nb = nve + (size_t)b * 65 * 512;

    unsigned long long acc[2] = {0ull, 0ull};
    unsigned long long acc64 = 0ull;

    const int arow = tid >> 2, ak4 = (tid & 3) * 4;
    const int brow1 = (tid + 256) >> 2, bk41 = ((tid + 256) & 3) * 4;
    const bool hasB1 = (tid + 256) < 260;
    float4 ra4, rb4[2];
    {
        if (tid < 64) ra4 = *reinterpret_cast<const float4*>(&Tb[arow * 512 + ak4]);
        rb4[0] = *reinterpret_cast<const float4*>(&Nb[arow * 512 + ak4]);
        if (hasB1) rb4[1] = *reinterpret_cast<const float4*>(&Nb[brow1 * 512 + bk41]);
        if (tid < 64) {
            As[0][ak4 + 0][arow] = ra4.x;
            As[0][ak4 + 1][arow] = ra4.y;
            As[0][ak4 + 2][arow] = ra4.z;
            As[0][ak4 + 3][arow] = ra4.w;
        }
        Bs[0][ak4 + 0][arow] = rb4[0].x;
        Bs[0][ak4 + 1][arow] = rb4[0].y;
        Bs[0][ak4 + 2][arow] = rb4[0].z;
        Bs[0][ak4 + 3][arow] = rb4[0].w;
        if (hasB1) {
            Bs[0][bk41 + 0][brow1] = rb4[1].x;
            Bs[0][bk41 + 1][brow1] = rb4[1].y;
            Bs[0][bk41 + 2][brow1] = rb4[1].z;
            Bs[0][bk41 + 3][brow1] = rb4[1].w;
        }
    }
    __syncthreads();

    for (int kt = 0; kt < 32; kt++) {
        const int cur = kt & 1, nxt = cur ^ 1;
        if (kt < 31) {
            int k0 = (kt + 1) * 16;
            if (tid < 64) ra4 = *reinterpret_cast<const float4*>(&Tb[arow * 512 + k0 + ak4]);
            rb4[0] = *reinterpret_cast<const float4*>(&Nb[arow * 512 + k0 + ak4]);
            if (hasB1) rb4[1] = *reinterpret_cast<const float4*>(&Nb[brow1 * 512 + k0 + bk41]);
        }
#pragma unroll
        for (int k = 0; k < 16; k++) {
            unsigned long long a = *reinterpret_cast<const unsigned long long*>(&As[cur][k][2 * tm]);
            float2 bv = *reinterpret_cast<const float2*>(&Bs[cur][k][2 * tn]);
            fma2(acc[0], a, bcast2(bv.x));
            fma2(acc[1], a, bcast2(bv.y));
            if (tn == 0) fma2(acc64, a, bcast2(Bs[cur][k][64]));
        }
        if (kt < 31) {
            if (tid < 64) {
                As[nxt][ak4 + 0][arow] = ra4.x;
                As[nxt][ak4 + 1][arow] = ra4.y;
                As[nxt][ak4 + 2][arow] = ra4.z;
                As[nxt][ak4 + 3][arow] = ra4.w;
            }
            Bs[nxt][ak4 + 0][arow] = rb4[0].x;
            Bs[nxt][ak4 + 1][arow] = rb4[0].y;
            Bs[nxt][ak4 + 2][arow] = rb4[0].z;
            Bs[nxt][ak4 + 3][arow] = rb4[0].w;
            if (hasB1) {
                Bs[nxt][bk41 + 0][brow1] = rb4[1].x;
                Bs[nxt][bk41 + 1][brow1] = rb4[1].y;
                Bs[nxt][bk41 + 2][brow1] = rb4[1].z;
                Bs[nxt][bk41 + 3][brow1] = rb4[1].w;
            }
            __syncthreads();
        }
    }

#pragma unroll
    for (int q = 0; q < 2; q++) {
        float2 v = unpk2(acc[q]);
        sS[2 * tm][2 * tn + q] = v.x;
        sS[2 * tm + 1][2 * tn + q] = v.y;
    }
    if (tn == 0) {
        float2 v = unpk2(acc64);
        sS[2 * tm][64] = v.x;
        sS[2 * tm + 1][64] = v.y;
    }
    __syncthreads();

    const int w = tid >> 5, lane = tid & 31;
    const unsigned FULL = 0xffffffffu;
    const float INV_SQRTD = 0.044194173824159216f;
    const float s0 = g_s0;
#pragma unroll
    for (int rr = 0; rr < 2; rr++) {
        int r = w * 2 + rr;
        int i = i0 + r;
        float base = su1[r] + s0;
        int j1 = 32 + lane;
        float L0 = (lane == i) ? 0.f : (sS[r][lane] + base + su2[lane]) * INV_SQRTD;
        float L1 = (j1 == i) ? 0.f : (sS[r][j1] + base + su2[j1]) * INV_SQRTD;
        float L2 = (lane == 0)
                       ? ((i == 64) ? 0.f : (sS[r][64] + base + su2[64]) * INV_SQRTD)
                       : -1e30f;
        float mx = fmaxf(L0, fmaxf(L1, L2));
        for (int o = 16; o; o >>= 1) mx = fmaxf(mx, __shfl_xor_sync(FULL, mx, o));
        float e0 = expf(L0 - mx);
        float e1 = expf(L1 - mx);
        float e2 = (lane == 0) ? expf(L2 - mx) : 0.f;
        float sm = e0 + e1 + e2;
        for (int o = 16; o; o >>= 1) sm += __shfl_xor_sync(FULL, sm, o);
        float inv = 1.0f / sm;
        unsigned bal0 = __ballot_sync(FULL, (lane >= 1) && (e0 * inv > 0.05f));
        unsigned bal1 = __ballot_sync(FULL, e1 * inv > 0.05f);
        unsigned bal2 = __ballot_sync(FULL, (lane == 0) && (e2 * inv > 0.05f));
        if (lane == 0) {
            unsigned long long m = ((unsigned long long)(bal0 >> 1)) |
                                   ((unsigned long long)bal1 << 31) |
                                   ((unsigned long long)(bal2 & 1u) << 63);
            m |= 1ull << (i - 1);
            g_rawmask[b * 64 + (i - 1)] = m;
        }
    }
}

// ----------------------------------------------------------------------------
// cluster: greedy sequential clustering per batch + leader/member outputs
// ----------------------------------------------------------------------------
__global__ __launch_bounds__(256) void cluster_kernel(float* __restrict__ out) {
    __shared__ unsigned long long sm[64];
    __shared__ unsigned long long sf[64];
    __shared__ unsigned long long sl;
    const int b = blockIdx.x;
    const int tid = threadIdx.x;
    if (tid < 64) sm[tid] = g_rawmask[b * 64 + tid];
    __syncthreads();
    if (tid == 0) {
        unsigned long long used = 0ull, lead = 0ull;
        for (int i = 0; i < 64; i++) {
            unsigned long long m = sm[i];
            if (!((used >> i) & 1ull)) {
                lead |= 1ull << i;
                used |= m;
                sf[i] = m;
            } else {
                sf[i] = 0ull;
            }
        }
        sl = lead;
    }
    __syncthreads();
    unsigned long long lead = sl;
    if (tid < 64) {
        out[LEADER_OFF + (size_t)b * 64 + tid] = ((lead >> tid) & 1ull) ? 1.0f : 0.0f;
        g_mmask[b * 64 + tid] = sf[tid];
    }
    for (int idx = tid; idx < 4096; idx += 256) {
        out[MEMBER_OFF + (size_t)b * 4096 + idx] =
            ((sf[idx >> 6] >> (idx & 63)) & 1ull) ? 1.0f : 0.0f;
    }
}

// ----------------------------------------------------------------------------
// expansion: write-bandwidth bound (~273 MB), streaming stores.
// ----------------------------------------------------------------------------
__global__ __launch_bounds__(256) void expand_kernel(const float* __restrict__ nve,
                                                     const float* __restrict__ cls,
                                                     float* __restrict__ out) {
    const int bi = blockIdx.x;
    const int b = bi >> 6;
    const unsigned long long mask = g_mmask[bi];
    const bool lead = (mask != 0ull);

    const float4* nve4 = reinterpret_cast<const float4*>(nve);
    const float4* cls4 = reinterpret_cast<const float4*>(cls);
    float4* out4 = reinterpret_cast<float4*>(out) + (size_t)bi * 65 * 128;

    const int quad = threadIdx.x & 127;
    const int sub = threadIdx.x >> 7;
    const float4 zero4 = make_float4(0.f, 0.f, 0.f, 0.f);

    for (int r = sub; r < 65; r += 2) {
        float4 v;
        if (r == 0) {
            v = lead ? cls4[quad] : zero4;
        } else {
            v = ((mask >> (r - 1)) & 1ull) ? nve4[((size_t)b * 65 + r) * 128 + quad]
                                           : zero4;
        }
        __stcs(&out4[(size_t)r * 128 + quad], v);
    }
}

// ----------------------------------------------------------------------------
extern "C" void kernel_launch(void* const* d_in, const int* in_sizes, int n_in,
                              void* d_out, int out_size) {
    // inputs: desc_embeddings, name_value_embeddings, Wq, bq, Wk, bk, cls
    const float* nve = (const float*)d_in[1];
    const float* Wq  = (const float*)d_in[2];
    const float* bq  = (const float*)d_in[3];
    const float* Wk  = (const float*)d_in[4];
    const float* bk  = (const float*)d_in[5];
    const float* cls = (const float*)d_in[6];
    float* out = (float*)d_out;

    cudaFuncSetAttribute(gemm_T_kernel, cudaFuncAttributeMaxDynamicSharedMemorySize,
                         GT_SMEM);

    prep_kernel<<<16, 256>>>(Wq, bq, Wk, bk);
    u_kernel<<<260, 256>>>(nve);
    gemm_C_kernel<<<dim3(8, 8, 4), 128>>>(Wq, Wk);
    gemm_T_kernel<<<dim3(17, 8), 128, GT_SMEM>>>(nve);
    score_kernel<<<dim3(4, BB), 256>>>(nve);
    cluster_kernel<<<BB, 256>>>(out);
    expand_kernel<<<BB * SS, 256>>>(nve, cls, out);
}

// round 15
// speedup vs baseline: 1.1517x; 1.0535x over previous
#include <cuda_runtime.h>
#include <math.h>

// ---------------------------------------------------------------------------
// SubgraphAttention — see prior rounds. All math fp32; GEMMs use packed
// fma.rn.f32x2 (bit-exact IEEE fp32).
// R15: keep split-K=4 gemm_C (R14 proved it saves ~10us); revert gemm_T to
// R11's unfused form (R14's 4-way fused staging cost +12us: C is re-read by
// 17 m-blocks, fusion multiplies traffic by reuse); reduce C partials in a
// dedicated high-ILP kernel (2 float4/thread, 8 indep LDGs, L2-resident).
// ---------------------------------------------------------------------------

#define BB 32
#define NN 65
#define SS 64
#define DD 512
#define MROWS (BB * NN)   // 2080

static const size_t OUT_ELEMS  = (size_t)BB * SS * NN * DD;    // 68,157,440
static const size_t LEADER_OFF = OUT_ELEMS;
static const size_t MEMBER_OFF = OUT_ELEMS + (size_t)BB * SS;

// gemm_T dynamic smem layout: As[2][32][130] then Bs[2][32][64]
#define TT_APAD 130
static const int GT_SMEM = (2 * 32 * TT_APAD + 2 * 32 * 64) * 4;  // 49,664 B

// ----------------------------- device scratch ------------------------------
__device__ float g_Cp[4][DD * DD];        // C split-K partials
__device__ float g_C[DD * DD];            // reduced C
__device__ float g_T[MROWS * DD];
__device__ float g_v1[DD];
__device__ float g_v2[DD];
__device__ float g_s0;
__device__ float g_u1[MROWS];
__device__ float g_u2[MROWS];
__device__ unsigned long long g_rawmask[BB * SS];
__device__ unsigned long long g_mmask[BB * SS];

// ----------------------------- f32x2 helpers -------------------------------
__device__ __forceinline__ void fma2(unsigned long long& d, unsigned long long a,
                                     unsigned long long b) {
    asm("fma.rn.f32x2 %0, %1, %2, %0;" : "+l"(d) : "l"(a), "l"(b));
}
__device__ __forceinline__ unsigned long long bcast2(float x) {
    unsigned long long r;
    asm("mov.b64 %0, {%1, %1};" : "=l"(r) : "f"(x));
    return r;
}
__device__ __forceinline__ float2 unpk2(unsigned long long v) {
    float2 r;
    asm("mov.b64 {%0, %1}, %2;" : "=f"(r.x), "=f"(r.y) : "l"(v));
    return r;
}

// ----------------------------------------------------------------------------
// prep: v1 = Wq^T bk ; v2 = Wk^T bq ; s0 = bq.bk   (16 blocks)
// ----------------------------------------------------------------------------
__global__ __launch_bounds__(256) void prep_kernel(const float* __restrict__ Wq,
                                                   const float* __restrict__ bq,
                                                   const float* __restrict__ Wk,
                                                   const float* __restrict__ bk) {
    __shared__ float sb[512];
    __shared__ float part[4][64];
    __shared__ float red[256];
    const int tid = threadIdx.x;
    const int mat = blockIdx.x >> 3;
    const int c0 = (blockIdx.x & 7) * 64;
    const float* W = mat ? Wk : Wq;
    const float* bv = mat ? bq : bk;

    sb[tid] = bv[tid];
    sb[tid + 256] = bv[tid + 256];
    __syncthreads();

    const int c = c0 + (tid & 63);
    const int q = tid >> 6;
    const int n0 = q * 128;
    float acc = 0.f;
#pragma unroll 8
    for (int n = 0; n < 128; n++) {
        acc += W[(n0 + n) * 512 + c] * sb[n0 + n];
    }
    part[q][tid & 63] = acc;
    __syncthreads();
    if (tid < 64) {
        float v = ((part[0][tid] + part[1][tid]) + part[2][tid]) + part[3][tid];
        (mat ? g_v2 : g_v1)[c0 + tid] = v;
    }

    if (blockIdx.x == 0) {
        red[tid] = bq[tid] * bk[tid] + bq[tid + 256] * bk[tid + 256];
        __syncthreads();
        for (int s = 128; s > 0; s >>= 1) {
            if (tid < s) red[tid] += red[tid + s];
            __syncthreads();
        }
        if (tid == 0) g_s0 = red[0];
    }
}

// ----------------------------------------------------------------------------
// u_kernel: u1[m] = nve[m,:].v1 ; u2[m] = nve[m,:].v2   (one warp per row)
// ----------------------------------------------------------------------------
__global__ __launch_bounds__(256) void u_kernel(const float* __restrict__ nve) {
    __shared__ float sv1[512], sv2[512];
    const int tid = threadIdx.x;
    for (int i = tid; i < 512; i += 256) {
        sv1[i] = g_v1[i];
        sv2[i] = g_v2[i];
    }
    __syncthreads();
    const int w = tid >> 5, lane = tid & 31;
    const int m = blockIdx.x * 8 + w;
    if (m < MROWS) {
        const float* row = nve + (size_t)m * 512;
        float p1 = 0.f, p2 = 0.f;
#pragma unroll
        for (int r = 0; r < 16; r++) {
            float x = row[r * 32 + lane];
            p1 += x * sv1[r * 32 + lane];
            p2 += x * sv2[r * 32 + lane];
        }
        for (int o = 16; o; o >>= 1) {
            p1 += __shfl_xor_sync(0xffffffffu, p1, o);
            p2 += __shfl_xor_sync(0xffffffffu, p2, o);
        }
        if (lane == 0) { g_u1[m] = p1; g_u2[m] = p2; }
    }
}

// ----------------------------------------------------------------------------
// gemm_C: Cp[z][m,n] = sum_{k in chunk z} Wq[k,m] * Wk[k,n]  (512x512x128)
// Split-K=4. BM=BN=64, BK=32, 128 thr, grid (8,8,4)=256. Tile 4Mx8N.
// ----------------------------------------------------------------------------
__global__ __launch_bounds__(128) void gemm_C_kernel(const float* __restrict__ Wq,
                                                     const float* __restrict__ Wk) {
    __shared__ __align__(16) float As[2][32][68];
    __shared__ __align__(16) float Bs[2][32][64];
    const int tid = threadIdx.x;
    const int tm = tid & 15;
    const int tn = tid >> 4;
    const int bm0 = blockIdx.x * 64;
    const int bn0 = blockIdx.y * 64;
    const int kbase = blockIdx.z * 128;

    unsigned long long acc[16];
#pragma unroll
    for (int i = 0; i < 16; i++) acc[i] = 0ull;

    float4 ra[4], rb[4];
#pragma unroll
    for (int it = 0; it < 4; it++) {
        int idx = tid + it * 128;
        int r = idx >> 4, c4 = (idx & 15) * 4;
        ra[it] = *reinterpret_cast<const float4*>(&Wq[(kbase + r) * 512 + bm0 + c4]);
        rb[it] = *reinterpret_cast<const float4*>(&Wk[(kbase + r) * 512 + bn0 + c4]);
    }
#pragma unroll
    for (int it = 0; it < 4; it++) {
        int idx = tid + it * 128;
        int r = idx >> 4, c4 = (idx & 15) * 4;
        *reinterpret_cast<float4*>(&As[0][r][c4]) = ra[it];
        *reinterpret_cast<float4*>(&Bs[0][r][c4]) = rb[it];
    }
    __syncthreads();

    for (int kt = 0; kt < 4; kt++) {
        const int cur = kt & 1, nxt = cur ^ 1;
        if (kt < 3) {
            int k0 = kbase + (kt + 1) * 32;
#pragma unroll
            for (int it = 0; it < 4; it++) {
                int idx = tid + it * 128;
                int r = idx >> 4, c4 = (idx & 15) * 4;
                ra[it] = *reinterpret_cast<const float4*>(&Wq[(k0 + r) * 512 + bm0 + c4]);
                rb[it] = *reinterpret_cast<const float4*>(&Wk[(k0 + r) * 512 + bn0 + c4]);
            }
        }
#pragma unroll
        for (int k = 0; k < 32; k++) {
            unsigned long long a0 = *reinterpret_cast<const unsigned long long*>(&As[cur][k][2 * tm]);
            unsigned long long a1 = *reinterpret_cast<const unsigned long long*>(&As[cur][k][2 * tm + 32]);
            float4 b0 = *reinterpret_cast<const float4*>(&Bs[cur][k][8 * tn]);
            float4 b1 = *reinterpret_cast<const float4*>(&Bs[cur][k][8 * tn + 4]);
            unsigned long long bb[8] = {bcast2(b0.x), bcast2(b0.y), bcast2(b0.z), bcast2(b0.w),
                                        bcast2(b1.x), bcast2(b1.y), bcast2(b1.z), bcast2(b1.w)};
#pragma unroll
            for (int n = 0; n < 8; n++) {
                fma2(acc[n], a0, bb[n]);
                fma2(acc[8 + n], a1, bb[n]);
            }
        }
        if (kt < 3) {
#pragma unroll
            for (int it = 0; it < 4; it++) {
                int idx = tid + it * 128;
                int r = idx >> 4, c4 = (idx & 15) * 4;
                *reinterpret_cast<float4*>(&As[nxt][r][c4]) = ra[it];
                *reinterpret_cast<float4*>(&Bs[nxt][r][c4]) = rb[it];
            }
            __syncthreads();
        }
    }
    float* dst = g_Cp[blockIdx.z];
#pragma unroll
    for (int p = 0; p < 2; p++) {
#pragma unroll
        for (int n = 0; n < 8; n++) {
            float2 v = unpk2(acc[p * 8 + n]);
            int m = bm0 + 2 * tm + 32 * p;
            int nc = bn0 + 8 * tn + n;
            dst[m * 512 + nc] = v.x;
            dst[(m + 1) * 512 + nc] = v.y;
        }
    }
}

// ----------------------------------------------------------------------------
// reduce_C: g_C = Cp0+Cp1+Cp2+Cp3, fixed order. 2 float4/thread => 8 indep
// LDG.128 in flight; partials are L2-resident (4 MB just written).
// Grid 128 x 256 thr: 32768 threads x 2 positions = 65536 float4.
// ----------------------------------------------------------------------------
__global__ __launch_bounds__(256) void reduce_C_kernel() {
    const int i = blockIdx.x * 256 + threadIdx.x;       // 0..32767
    const int j = i + 32768;
    const float4* p0 = reinterpret_cast<const float4*>(g_Cp[0]);
    const float4* p1 = reinterpret_cast<const float4*>(g_Cp[1]);
    const float4* p2 = reinterpret_cast<const float4*>(g_Cp[2]);
    const float4* p3 = reinterpret_cast<const float4*>(g_Cp[3]);
    float4 a0 = p0[i], a1 = p1[i], a2 = p2[i], a3 = p3[i];
    float4 b0 = p0[j], b1 = p1[j], b2 = p2[j], b3 = p3[j];
    float4 ra, rbv;
    ra.x = ((a0.x + a1.x) + a2.x) + a3.x;
    ra.y = ((a0.y + a1.y) + a2.y) + a3.y;
    ra.z = ((a0.z + a1.z) + a2.z) + a3.z;
    ra.w = ((a0.w + a1.w) + a2.w) + a3.w;
    rbv.x = ((b0.x + b1.x) + b2.x) + b3.x;
    rbv.y = ((b0.y + b1.y) + b2.y) + b3.y;
    rbv.z = ((b0.z + b1.z) + b2.z) + b3.z;
    rbv.w = ((b0.w + b1.w) + b2.w) + b3.w;
    reinterpret_cast<float4*>(g_C)[i] = ra;
    reinterpret_cast<float4*>(g_C)[j] = rbv;
}

// ----------------------------------------------------------------------------
// gemm_T: T[m,n] = sum_k nve[m,k] * C[k,n]  (NN, 2080x512x512)
// BM=128, BN=64, BK=32, 128 thr, grid (17,8)=136. Thread tile 8Mx8N.
// DYNAMIC smem 49,664 B. Exact R11 kernel (best measured: 41.9us).
// ----------------------------------------------------------------------------
__global__ __launch_bounds__(128) void gemm_T_kernel(const float* __restrict__ nve) {
    extern __shared__ __align__(16) float dsm[];
    float* Asf = dsm;                          // [2][32][130]
    float* Bsf = dsm + 2 * 32 * TT_APAD;       // [2][32][64]
#define AS_T(buf, k, m) Asf[((buf) * 32 + (k)) * TT_APAD + (m)]
#define BS_T(buf, k, n) Bsf[((buf) * 32 + (k)) * 64 + (n)]

    const int tid = threadIdx.x;
    const int tm = tid & 15;
    const int tn = tid >> 4;
    const int m0 = blockIdx.x * 128;
    const int n0 = blockIdx.y * 64;

    unsigned long long acc[32];
#pragma unroll
    for (int i = 0; i < 32; i++) acc[i] = 0ull;

    const float4 z4 = make_float4(0.f, 0.f, 0.f, 0.f);
    float4 ra[8], rb[4];
#pragma unroll
    for (int it = 0; it < 8; it++) {
        int idx = tid + it * 128;
        int m = m0 + (idx >> 3), k4 = (idx & 7) * 4;
        ra[it] = (m < MROWS) ? *reinterpret_cast<const float4*>(&nve[m * 512 + k4]) : z4;
    }
#pragma unroll
    for (int it = 0; it < 4; it++) {
        int idx = tid + it * 128;
        int r = idx >> 4, c4 = (idx & 15) * 4;
        rb[it] = *reinterpret_cast<const float4*>(&g_C[r * 512 + n0 + c4]);
    }
#pragma unroll
    for (int it = 0; it < 8; it++) {
        int idx = tid + it * 128;
        int ml = idx >> 3, k4 = (idx & 7) * 4;
        AS_T(0, k4 + 0, ml) = ra[it].x;
        AS_T(0, k4 + 1, ml) = ra[it].y;
        AS_T(0, k4 + 2, ml) = ra[it].z;
        AS_T(0, k4 + 3, ml) = ra[it].w;
    }
#pragma unroll
    for (int it = 0; it < 4; it++) {
        int idx = tid + it * 128;
        int r = idx >> 4, c4 = (idx & 15) * 4;
        *reinterpret_cast<float4*>(&BS_T(0, r, c4)) = rb[it];
    }
    __syncthreads();

    for (int kt = 0; kt < 16; kt++) {
        const int cur = kt & 1, nxt = cur ^ 1;
        if (kt < 15) {
            int k0 = (kt + 1) * 32;
#pragma unroll
            for (int it = 0; it < 8; it++) {
                int idx = tid + it * 128;
                int m = m0 + (idx >> 3), k4 = (idx & 7) * 4;
                ra[it] = (m < MROWS)
                             ? *reinterpret_cast<const float4*>(&nve[m * 512 + k0 + k4])
                             : z4;
            }
#pragma unroll
            for (int it = 0; it < 4; it++) {
                int idx = tid + it * 128;
                int r = idx >> 4, c4 = (idx & 15) * 4;
                rb[it] = *reinterpret_cast<const float4*>(&g_C[(k0 + r) * 512 + n0 + c4]);
            }
        }
#pragma unroll
        for (int k = 0; k < 32; k++) {
            unsigned long long a[4];
#pragma unroll
            for (int p = 0; p < 4; p++)
                a[p] = *reinterpret_cast<const unsigned long long*>(&AS_T(cur, k, 2 * tm + 32 * p));
            float4 b0 = *reinterpret_cast<const float4*>(&BS_T(cur, k, 8 * tn));
            float4 b1 = *reinterpret_cast<const float4*>(&BS_T(cur, k, 8 * tn + 4));
            unsigned long long bb[8] = {bcast2(b0.x), bcast2(b0.y), bcast2(b0.z), bcast2(b0.w),
                                        bcast2(b1.x), bcast2(b1.y), bcast2(b1.z), bcast2(b1.w)};
#pragma unroll
            for (int p = 0; p < 4; p++) {
#pragma unroll
                for (int n = 0; n < 8; n++) fma2(acc[p * 8 + n], a[p], bb[n]);
            }
        }
        if (kt < 15) {
#pragma unroll
            for (int it = 0; it < 8; it++) {
                int idx = tid + it * 128;
                int ml = idx >> 3, k4 = (idx & 7) * 4;
                AS_T(nxt, k4 + 0, ml) = ra[it].x;
                AS_T(nxt, k4 + 1, ml) = ra[it].y;
                AS_T(nxt, k4 + 2, ml) = ra[it].z;
                AS_T(nxt, k4 + 3, ml) = ra[it].w;
            }
#pragma unroll
            for (int it = 0; it < 4; it++) {
                int idx = tid + it * 128;
                int r = idx >> 4, c4 = (idx & 15) * 4;
                *reinterpret_cast<float4*>(&BS_T(nxt, r, c4)) = rb[it];
            }
            __syncthreads();
        }
    }
#pragma unroll
    for (int p = 0; p < 4; p++) {
#pragma unroll
        for (int n = 0; n < 8; n++) {
            float2 v = unpk2(acc[p * 8 + n]);
            int m = m0 + 2 * tm + 32 * p;
            int nc = n0 + 8 * tn + n;
            if (m < MROWS) g_T[m * 512 + nc] = v.x;
            if (m + 1 < MROWS) g_T[(m + 1) * 512 + nc] = v.y;
        }
    }
#undef AS_T
#undef BS_T
}

// ----------------------------------------------------------------------------
// score_kernel: S[i,j] = T[b,i,:].nve[b,j,:] for 16 i-rows, j in [0,65);
// softmax + threshold -> raw masks. Grid (4, BB) = 128 blocks. (R11 version.)
// ----------------------------------------------------------------------------
__global__ __launch_bounds__(256) void score_kernel(const float* __restrict__ nve) {
    __shared__ __align__(16) float As[2][16][18];
    __shared__ __align__(16) float Bs[2][16][68];
    __shared__ float sS[16][68];
    __shared__ float su1[16];
    __shared__ float su2[65];

    const int b = blockIdx.y;
    const int i0 = 1 + 16 * blockIdx.x;
    const int tid = threadIdx.x;
    const int tm = tid & 7;
    const int tn = tid >> 3;

    if (tid < 16) su1[tid] = g_u1[b * 65 + i0 + tid];
    else if (tid < 16 + 65) su2[tid - 16] = g_u2[b * 65 + (tid - 16)];

    const float* Tb = g_T + ((size_t)b * 65 + i0) * 512;
    const float* Nb = nve + (size_t)b * 65 * 512;

    unsigned long long acc[2] = {0ull, 0ull};
    unsigned long long acc64 = 0ull;

    const int arow = tid >> 2, ak4 = (tid & 3) * 4;
    const int brow1 = (tid + 256) >> 2, bk41 = ((tid + 256) & 3) * 4;
    const bool hasB1 = (tid + 256) < 260;
    float4 ra4, rb4[2];
    {
        if (tid < 64) ra4 = *reinterpret_cast<const float4*>(&Tb[arow * 512 + ak4]);
        rb4[0] = *reinterpret_cast<const float4*>(&Nb[arow * 512 + ak4]);
        if (hasB1) rb4[1] = *reinterpret_cast<const float4*>(&Nb[brow1 * 512 + bk41]);
        if (tid < 64) {
            As[0][ak4 + 0][arow] = ra4.x;
            As[0][ak4 + 1][arow] = ra4.y;
            As[0][ak4 + 2][arow] = ra4.z;
            As[0][ak4 + 3][arow] = ra4.w;
        }
        Bs[0][ak4 + 0][arow] = rb4[0].x;
        Bs[0][ak4 + 1][arow] = rb4[0].y;
        Bs[0][ak4 + 2][arow] = rb4[0].z;
        Bs[0][ak4 + 3][arow] = rb4[0].w;
        if (hasB1) {
            Bs[0][bk41 + 0][brow1] = rb4[1].x;
            Bs[0][bk41 + 1][brow1] = rb4[1].y;
            Bs[0][bk41 + 2][brow1] = rb4[1].z;
            Bs[0][bk41 + 3][brow1] = rb4[1].w;
        }
    }
    __syncthreads();

    for (int kt = 0; kt < 32; kt++) {
        const int cur = kt & 1, nxt = cur ^ 1;
        if (kt < 31) {
            int k0 = (kt + 1) * 16;
            if (tid < 64) ra4 = *reinterpret_cast<const float4*>(&Tb[arow * 512 + k0 + ak4]);
            rb4[0] = *reinterpret_cast<const float4*>(&Nb[arow * 512 + k0 + ak4]);
            if (hasB1) rb4[1] = *reinterpret_cast<const float4*>(&Nb[brow1 * 512 + k0 + bk41]);
        }
#pragma unroll
        for (int k = 0; k < 16; k++) {
            unsigned long long a = *reinterpret_cast<const unsigned long long*>(&As[cur][k][2 * tm]);
            float2 bv = *reinterpret_cast<const float2*>(&Bs[cur][k][2 * tn]);
            fma2(acc[0], a, bcast2(bv.x));
            fma2(acc[1], a, bcast2(bv.y));
            if (tn == 0) fma2(acc64, a, bcast2(Bs[cur][k][64]));
        }
        if (kt < 31) {
            if (tid < 64) {
                As[nxt][ak4 + 0][arow] = ra4.x;
                As[nxt][ak4 + 1][arow] = ra4.y;
                As[nxt][ak4 + 2][arow] = ra4.z;
                As[nxt][ak4 + 3][arow] = ra4.w;
            }
            Bs[nxt][ak4 + 0][arow] = rb4[0].x;
            Bs[nxt][ak4 + 1][arow] = rb4[0].y;
            Bs[nxt][ak4 + 2][arow] = rb4[0].z;
            Bs[nxt][ak4 + 3][arow] = rb4[0].w;
            if (hasB1) {
                Bs[nxt][bk41 + 0][brow1] = rb4[1].x;
                Bs[nxt][bk41 + 1][brow1] = rb4[1].y;
                Bs[nxt][bk41 + 2][brow1] = rb4[1].z;
                Bs[nxt][bk41 + 3][brow1] = rb4[1].w;
            }
            __syncthreads();
        }
    }

#pragma unroll
    for (int q = 0; q < 2; q++) {
        float2 v = unpk2(acc[q]);
        sS[2 * tm][2 * tn + q] = v.x;
        sS[2 * tm + 1][2 * tn + q] = v.y;
    }
    if (tn == 0) {
        float2 v = unpk2(acc64);
        sS[2 * tm][64] = v.x;
        sS[2 * tm + 1][64] = v.y;
    }
    __syncthreads();

    const int w = tid >> 5, lane = tid & 31;
    const unsigned FULL = 0xffffffffu;
    const float INV_SQRTD = 0.044194173824159216f;
    const float s0 = g_s0;
#pragma unroll
    for (int rr = 0; rr < 2; rr++) {
        int r = w * 2 + rr;
        int i = i0 + r;
        float base = su1[r] + s0;
        int j1 = 32 + lane;
        float L0 = (lane == i) ? 0.f : (sS[r][lane] + base + su2[lane]) * INV_SQRTD;
        float L1 = (j1 == i) ? 0.f : (sS[r][j1] + base + su2[j1]) * INV_SQRTD;
        float L2 = (lane == 0)
                       ? ((i == 64) ? 0.f : (sS[r][64] + base + su2[64]) * INV_SQRTD)
                       : -1e30f;
        float mx = fmaxf(L0, fmaxf(L1, L2));
        for (int o = 16; o; o >>= 1) mx = fmaxf(mx, __shfl_xor_sync(FULL, mx, o));
        float e0 = expf(L0 - mx);
        float e1 = expf(L1 - mx);
        float e2 = (lane == 0) ? expf(L2 - mx) : 0.f;
        float sm = e0 + e1 + e2;
        for (int o = 16; o; o >>= 1) sm += __shfl_xor_sync(FULL, sm, o);
        float inv = 1.0f / sm;
        unsigned bal0 = __ballot_sync(FULL, (lane >= 1) && (e0 * inv > 0.05f));
        unsigned bal1 = __ballot_sync(FULL, e1 * inv > 0.05f);
        unsigned bal2 = __ballot_sync(FULL, (lane == 0) && (e2 * inv > 0.05f));
        if (lane == 0) {
            unsigned long long m = ((unsigned long long)(bal0 >> 1)) |
                                   ((unsigned long long)bal1 << 31) |
                                   ((unsigned long long)(bal2 & 1u) << 63);
            m |= 1ull << (i - 1);
            g_rawmask[b * 64 + (i - 1)] = m;
        }
    }
}

// ----------------------------------------------------------------------------
// cluster: greedy sequential clustering per batch + leader/member outputs
// ----------------------------------------------------------------------------
__global__ __launch_bounds__(256) void cluster_kernel(float* __restrict__ out) {
    __shared__ unsigned long long sm[64];
    __shared__ unsigned long long sf[64];
    __shared__ unsigned long long sl;
    const int b = blockIdx.x;
    const int tid = threadIdx.x;
    if (tid < 64) sm[tid] = g_rawmask[b * 64 + tid];
    __syncthreads();
    if (tid == 0) {
        unsigned long long used = 0ull, lead = 0ull;
        for (int i = 0; i < 64; i++) {
            unsigned long long m = sm[i];
            if (!((used >> i) & 1ull)) {
                lead |= 1ull << i;
                used |= m;
                sf[i] = m;
            } else {
                sf[i] = 0ull;
            }
        }
        sl = lead;
    }
    __syncthreads();
    unsigned long long lead = sl;
    if (tid < 64) {
        out[LEADER_OFF + (size_t)b * 64 + tid] = ((lead >> tid) & 1ull) ? 1.0f : 0.0f;
        g_mmask[b * 64 + tid] = sf[tid];
    }
    for (int idx = tid; idx < 4096; idx += 256) {
        out[MEMBER_OFF + (size_t)b * 4096 + idx] =
            ((sf[idx >> 6] >> (idx & 63)) & 1ull) ? 1.0f : 0.0f;
    }
}

// ----------------------------------------------------------------------------
// expansion: write-bandwidth bound (~273 MB), streaming stores.
// ----------------------------------------------------------------------------
__global__ __launch_bounds__(256) void expand_kernel(const float* __restrict__ nve,
                                                     const float* __restrict__ cls,
                                                     float* __restrict__ out) {
    const int bi = blockIdx.x;
    const int b = bi >> 6;
    const unsigned long long mask = g_mmask[bi];
    const bool lead = (mask != 0ull);

    const float4* nve4 = reinterpret_cast<const float4*>(nve);
    const float4* cls4 = reinterpret_cast<const float4*>(cls);
    float4* out4 = reinterpret_cast<float4*>(out) + (size_t)bi * 65 * 128;

    const int quad = threadIdx.x & 127;
    const int sub = threadIdx.x >> 7;
    const float4 zero4 = make_float4(0.f, 0.f, 0.f, 0.f);

    for (int r = sub; r < 65; r += 2) {
        float4 v;
        if (r == 0) {
            v = lead ? cls4[quad] : zero4;
        } else {
            v = ((mask >> (r - 1)) & 1ull) ? nve4[((size_t)b * 65 + r) * 128 + quad]
                                           : zero4;
        }
        __stcs(&out4[(size_t)r * 128 + quad], v);
    }
}

// ----------------------------------------------------------------------------
extern "C" void kernel_launch(void* const* d_in, const int* in_sizes, int n_in,
                              void* d_out, int out_size) {
    // inputs: desc_embeddings, name_value_embeddings, Wq, bq, Wk, bk, cls
    const float* nve = (const float*)d_in[1];
    const float* Wq  = (const float*)d_in[2];
    const float* bq  = (const float*)d_in[3];
    const float* Wk  = (const float*)d_in[4];
    const float* bk  = (const float*)d_in[5];
    const float* cls = (const float*)d_in[6];
    float* out = (float*)d_out;

    cudaFuncSetAttribute(gemm_T_kernel, cudaFuncAttributeMaxDynamicSharedMemorySize,
                         GT_SMEM);

    prep_kernel<<<16, 256>>>(Wq, bq, Wk, bk);
    u_kernel<<<260, 256>>>(nve);
    gemm_C_kernel<<<dim3(8, 8, 4), 128>>>(Wq, Wk);
    reduce_C_kernel<<<128, 256>>>();
    gemm_T_kernel<<<dim3(17, 8), 128, GT_SMEM>>>(nve);
    score_kernel<<<dim3(4, BB), 256>>>(nve);
    cluster_kernel<<<BB, 256>>>(out);
    expand_kernel<<<BB * SS, 256>>>(nve, cls, out);
}

// round 16
// speedup vs baseline: 1.2246x; 1.0633x over previous
#include <cuda_runtime.h>
#include <math.h>

// ---------------------------------------------------------------------------
// SubgraphAttention — see prior rounds. All math fp32; GEMMs use packed
// fma.rn.f32x2 (bit-exact IEEE fp32).
// R16: graph-node reduction. Budget audit: ~14us of the 128.5 lives in
// inter-kernel gaps (8 nodes). Merge prep+gemm_C (stage1) and u+reduce_C
// (stage2) via blockIdx dispatch -> 6 nodes; reduce gets 4 float4/thread
// (16 indep LDGs). gemm_T/score/cluster/expand = R15 best-measured forms.
// ---------------------------------------------------------------------------

#define BB 32
#define NN 65
#define SS 64
#define DD 512
#define MROWS (BB * NN)   // 2080

static const size_t OUT_ELEMS  = (size_t)BB * SS * NN * DD;    // 68,157,440
static const size_t LEADER_OFF = OUT_ELEMS;
static const size_t MEMBER_OFF = OUT_ELEMS + (size_t)BB * SS;

// gemm_T dynamic smem layout: As[2][32][130] then Bs[2][32][64]
#define TT_APAD 130
static const int GT_SMEM = (2 * 32 * TT_APAD + 2 * 32 * 64) * 4;  // 49,664 B

// ----------------------------- device scratch ------------------------------
__device__ float g_Cp[4][DD * DD];        // C split-K partials
__device__ float g_C[DD * DD];            // reduced C
__device__ float g_T[MROWS * DD];
__device__ float g_v1[DD];
__device__ float g_v2[DD];
__device__ float g_s0;
__device__ float g_u1[MROWS];
__device__ float g_u2[MROWS];
__device__ unsigned long long g_rawmask[BB * SS];
__device__ unsigned long long g_mmask[BB * SS];

// ----------------------------- f32x2 helpers -------------------------------
__device__ __forceinline__ void fma2(unsigned long long& d, unsigned long long a,
                                     unsigned long long b) {
    asm("fma.rn.f32x2 %0, %1, %2, %0;" : "+l"(d) : "l"(a), "l"(b));
}
__device__ __forceinline__ unsigned long long bcast2(float x) {
    unsigned long long r;
    asm("mov.b64 %0, {%1, %1};" : "=l"(r) : "f"(x));
    return r;
}
__device__ __forceinline__ float2 unpk2(unsigned long long v) {
    float2 r;
    asm("mov.b64 {%0, %1}, %2;" : "=f"(r.x), "=f"(r.y) : "l"(v));
    return r;
}

// ----------------------------------------------------------------------------
// stage1: blocks 0..31 = prep (v1/v2/s0); blocks 32..287 = gemm_C split-K=4.
// 128 threads per block.
//   prep block bx: mat = bx>>4, cols [(bx&15)*32, +32). Row quarters q=tid>>5
//   (identical per-element summation order to R15's prep). Block 0 also does
//   s0 (tree order differs ~1ulp; s0 is softmax-shift-invariant per row).
//   gemm_C block g = bx-32: bm=(g&7)*64, bn=((g>>3)&7)*64, kz=(g>>6)*128.
// ----------------------------------------------------------------------------
__global__ __launch_bounds__(128) void stage1_kernel(const float* __restrict__ Wq,
                                                     const float* __restrict__ bq,
                                                     const float* __restrict__ Wk,
                                                     const float* __restrict__ bk) {
    const int tid = threadIdx.x;
    const int bx = blockIdx.x;

    if (bx < 32) {
        __shared__ float sb[512];
        __shared__ float part[4][32];
        __shared__ float red[128];
        const int mat = bx >> 4;
        const int c0 = (bx & 15) * 32;
        const float* W = mat ? Wk : Wq;
        const float* bv = mat ? bq : bk;

        for (int i = tid; i < 512; i += 128) sb[i] = bv[i];
        __syncthreads();

        const int c = c0 + (tid & 31);
        const int q = tid >> 5;
        const int n0 = q * 128;
        float acc = 0.f;
#pragma unroll 8
        for (int n = 0; n < 128; n++) {
            acc += W[(n0 + n) * 512 + c] * sb[n0 + n];
        }
        part[q][tid & 31] = acc;
        __syncthreads();
        if (tid < 32) {
            float v = ((part[0][tid] + part[1][tid]) + part[2][tid]) + part[3][tid];
            (mat ? g_v2 : g_v1)[c0 + tid] = v;
        }
        if (bx == 0) {
            red[tid] = bq[tid] * bk[tid] + bq[tid + 128] * bk[tid + 128] +
                       bq[tid + 256] * bk[tid + 256] + bq[tid + 384] * bk[tid + 384];
            __syncthreads();
            for (int s = 64; s > 0; s >>= 1) {
                if (tid < s) red[tid] += red[tid + s];
                __syncthreads();
            }
            if (tid == 0) g_s0 = red[0];
        }
        return;
    }

    // ---- gemm_C branch ----
    __shared__ __align__(16) float As[2][32][68];
    __shared__ __align__(16) float Bs[2][32][64];
    const int g = bx - 32;
    const int tm = tid & 15;
    const int tn = tid >> 4;
    const int bm0 = (g & 7) * 64;
    const int bn0 = ((g >> 3) & 7) * 64;
    const int kbase = (g >> 6) * 128;

    unsigned long long acc[16];
#pragma unroll
    for (int i = 0; i < 16; i++) acc[i] = 0ull;

    float4 ra[4], rb[4];
#pragma unroll
    for (int it = 0; it < 4; it++) {
        int idx = tid + it * 128;
        int r = idx >> 4, c4 = (idx & 15) * 4;
        ra[it] = *reinterpret_cast<const float4*>(&Wq[(kbase + r) * 512 + bm0 + c4]);
        rb[it] = *reinterpret_cast<const float4*>(&Wk[(kbase + r) * 512 + bn0 + c4]);
    }
#pragma unroll
    for (int it = 0; it < 4; it++) {
        int idx = tid + it * 128;
        int r = idx >> 4, c4 = (idx & 15) * 4;
        *reinterpret_cast<float4*>(&As[0][r][c4]) = ra[it];
        *reinterpret_cast<float4*>(&Bs[0][r][c4]) = rb[it];
    }
    __syncthreads();

    for (int kt = 0; kt < 4; kt++) {
        const int cur = kt & 1, nxt = cur ^ 1;
        if (kt < 3) {
            int k0 = kbase + (kt + 1) * 32;
#pragma unroll
            for (int it = 0; it < 4; it++) {
                int idx = tid + it * 128;
                int r = idx >> 4, c4 = (idx & 15) * 4;
                ra[it] = *reinterpret_cast<const float4*>(&Wq[(k0 + r) * 512 + bm0 + c4]);
                rb[it] = *reinterpret_cast<const float4*>(&Wk[(k0 + r) * 512 + bn0 + c4]);
            }
        }
#pragma unroll
        for (int k = 0; k < 32; k++) {
            unsigned long long a0 = *reinterpret_cast<const unsigned long long*>(&As[cur][k][2 * tm]);
            unsigned long long a1 = *reinterpret_cast<const unsigned long long*>(&As[cur][k][2 * tm + 32]);
            float4 b0 = *reinterpret_cast<const float4*>(&Bs[cur][k][8 * tn]);
            float4 b1 = *reinterpret_cast<const float4*>(&Bs[cur][k][8 * tn + 4]);
            unsigned long long bb[8] = {bcast2(b0.x), bcast2(b0.y), bcast2(b0.z), bcast2(b0.w),
                                        bcast2(b1.x), bcast2(b1.y), bcast2(b1.z), bcast2(b1.w)};
#pragma unroll
            for (int n = 0; n < 8; n++) {
                fma2(acc[n], a0, bb[n]);
                fma2(acc[8 + n], a1, bb[n]);
            }
        }
        if (kt < 3) {
#pragma unroll
            for (int it = 0; it < 4; it++) {
                int idx = tid + it * 128;
                int r = idx >> 4, c4 = (idx & 15) * 4;
                *reinterpret_cast<float4*>(&As[nxt][r][c4]) = ra[it];
                *reinterpret_cast<float4*>(&Bs[nxt][r][c4]) = rb[it];
            }
            __syncthreads();
        }
    }
    float* dst = g_Cp[g >> 6];
#pragma unroll
    for (int p = 0; p < 2; p++) {
#pragma unroll
        for (int n = 0; n < 8; n++) {
            float2 v = unpk2(acc[p * 8 + n]);
            int m = bm0 + 2 * tm + 32 * p;
            int nc = bn0 + 8 * tn + n;
            dst[m * 512 + nc] = v.x;
            dst[(m + 1) * 512 + nc] = v.y;
        }
    }
}

// ----------------------------------------------------------------------------
// stage2: blocks 0..519 = u (4 rows per block, same per-row dot order);
// blocks 520..647 = reduce_C (4 float4/thread, 16 indep LDGs, fixed order).
// 128 threads per block.
// ----------------------------------------------------------------------------
__global__ __launch_bounds__(128) void stage2_kernel(const float* __restrict__ nve) {
    const int tid = threadIdx.x;
    const int bx = blockIdx.x;

    if (bx < 520) {
        __shared__ float sv1[512], sv2[512];
        for (int i = tid; i < 512; i += 128) {
            sv1[i] = g_v1[i];
            sv2[i] = g_v2[i];
        }
        __syncthreads();
        const int w = tid >> 5, lane = tid & 31;
        const int m = bx * 4 + w;          // < 2080 always
        const float* row = nve + (size_t)m * 512;
        float p1 = 0.f, p2 = 0.f;
#pragma unroll
        for (int r = 0; r < 16; r++) {
            float x = row[r * 32 + lane];
            p1 += x * sv1[r * 32 + lane];
            p2 += x * sv2[r * 32 + lane];
        }
        for (int o = 16; o; o >>= 1) {
            p1 += __shfl_xor_sync(0xffffffffu, p1, o);
            p2 += __shfl_xor_sync(0xffffffffu, p2, o);
        }
        if (lane == 0) { g_u1[m] = p1; g_u2[m] = p2; }
        return;
    }

    // ---- reduce_C branch: 4 positions per thread, 16384 apart ----
    const int base = (bx - 520) * 128 + tid;    // 0..16383
    const float4* p0 = reinterpret_cast<const float4*>(g_Cp[0]);
    const float4* p1 = reinterpret_cast<const float4*>(g_Cp[1]);
    const float4* p2 = reinterpret_cast<const float4*>(g_Cp[2]);
    const float4* p3 = reinterpret_cast<const float4*>(g_Cp[3]);
    float4* dst = reinterpret_cast<float4*>(g_C);
#pragma unroll
    for (int q = 0; q < 4; q++) {
        int i = base + q * 16384;
        float4 a = p0[i], b = p1[i], c = p2[i], d = p3[i];
        float4 r;
        r.x = ((a.x + b.x) + c.x) + d.x;
        r.y = ((a.y + b.y) + c.y) + d.y;
        r.z = ((a.z + b.z) + c.z) + d.z;
        r.w = ((a.w + b.w) + c.w) + d.w;
        dst[i] = r;
    }
}

// ----------------------------------------------------------------------------
// gemm_T: T[m,n] = sum_k nve[m,k] * C[k,n]  (NN, 2080x512x512)
// BM=128, BN=64, BK=32, 128 thr, grid (17,8)=136. Thread tile 8Mx8N.
// DYNAMIC smem 49,664 B. Exact R11/R15 kernel (best measured: 41.9us).
// ----------------------------------------------------------------------------
__global__ __launch_bounds__(128) void gemm_T_kernel(const float* __restrict__ nve) {
    extern __shared__ __align__(16) float dsm[];
    float* Asf = dsm;                          // [2][32][130]
    float* Bsf = dsm + 2 * 32 * TT_APAD;       // [2][32][64]
#define AS_T(buf, k, m) Asf[((buf) * 32 + (k)) * TT_APAD + (m)]
#define BS_T(buf, k, n) Bsf[((buf) * 32 + (k)) * 64 + (n)]

    const int tid = threadIdx.x;
    const int tm = tid & 15;
    const int tn = tid >> 4;
    const int m0 = blockIdx.x * 128;
    const int n0 = blockIdx.y * 64;

    unsigned long long acc[32];
#pragma unroll
    for (int i = 0; i < 32; i++) acc[i] = 0ull;

    const float4 z4 = make_float4(0.f, 0.f, 0.f, 0.f);
    float4 ra[8], rb[4];
#pragma unroll
    for (int it = 0; it < 8; it++) {
        int idx = tid + it * 128;
        int m = m0 + (idx >> 3), k4 = (idx & 7) * 4;
        ra[it] = (m < MROWS) ? *reinterpret_cast<const float4*>(&nve[m * 512 + k4]) : z4;
    }
#pragma unroll
    for (int it = 0; it < 4; it++) {
        int idx = tid + it * 128;
        int r = idx >> 4, c4 = (idx & 15) * 4;
        rb[it] = *reinterpret_cast<const float4*>(&g_C[r * 512 + n0 + c4]);
    }
#pragma unroll
    for (int it = 0; it < 8; it++) {
        int idx = tid + it * 128;
        int ml = idx >> 3, k4 = (idx & 7) * 4;
        AS_T(0, k4 + 0, ml) = ra[it].x;
        AS_T(0, k4 + 1, ml) = ra[it].y;
        AS_T(0, k4 + 2, ml) = ra[it].z;
        AS_T(0, k4 + 3, ml) = ra[it].w;
    }
#pragma unroll
    for (int it = 0; it < 4; it++) {
        int idx = tid + it * 128;
        int r = idx >> 4, c4 = (idx & 15) * 4;
        *reinterpret_cast<float4*>(&BS_T(0, r, c4)) = rb[it];
    }
    __syncthreads();

    for (int kt = 0; kt < 16; kt++) {
        const int cur = kt & 1, nxt = cur ^ 1;
        if (kt < 15) {
            int k0 = (kt + 1) * 32;
#pragma unroll
            for (int it = 0; it < 8; it++) {
                int idx = tid + it * 128;
                int m = m0 + (idx >> 3), k4 = (idx & 7) * 4;
                ra[it] = (m < MROWS)
                             ? *reinterpret_cast<const float4*>(&nve[m * 512 + k0 + k4])
                             : z4;
            }
#pragma unroll
            for (int it = 0; it < 4; it++) {
                int idx = tid + it * 128;
                int r = idx >> 4, c4 = (idx & 15) * 4;
                rb[it] = *reinterpret_cast<const float4*>(&g_C[(k0 + r) * 512 + n0 + c4]);
            }
        }
#pragma unroll
        for (int k = 0; k < 32; k++) {
            unsigned long long a[4];
#pragma unroll
            for (int p = 0; p < 4; p++)
                a[p] = *reinterpret_cast<const unsigned long long*>(&AS_T(cur, k, 2 * tm + 32 * p));
            float4 b0 = *reinterpret_cast<const float4*>(&BS_T(cur, k, 8 * tn));
            float4 b1 = *reinterpret_cast<const float4*>(&BS_T(cur, k, 8 * tn + 4));
            unsigned long long bb[8] = {bcast2(b0.x), bcast2(b0.y), bcast2(b0.z), bcast2(b0.w),
                                        bcast2(b1.x), bcast2(b1.y), bcast2(b1.z), bcast2(b1.w)};
#pragma unroll
            for (int p = 0; p < 4; p++) {
#pragma unroll
                for (int n = 0; n < 8; n++) fma2(acc[p * 8 + n], a[p], bb[n]);
            }
        }
        if (kt < 15) {
#pragma unroll
            for (int it = 0; it < 8; it++) {
                int idx = tid + it * 128;
                int ml = idx >> 3, k4 = (idx & 7) * 4;
                AS_T(nxt, k4 + 0, ml) = ra[it].x;
                AS_T(nxt, k4 + 1, ml) = ra[it].y;
                AS_T(nxt, k4 + 2, ml) = ra[it].z;
                AS_T(nxt, k4 + 3, ml) = ra[it].w;
            }
#pragma unroll
            for (int it = 0; it < 4; it++) {
                int idx = tid + it * 128;
                int r = idx >> 4, c4 = (idx & 15) * 4;
                *reinterpret_cast<float4*>(&BS_T(nxt, r, c4)) = rb[it];
            }
            __syncthreads();
        }
    }
#pragma unroll
    for (int p = 0; p < 4; p++) {
#pragma unroll
        for (int n = 0; n < 8; n++) {
            float2 v = unpk2(acc[p * 8 + n]);
            int m = m0 + 2 * tm + 32 * p;
            int nc = n0 + 8 * tn + n;
            if (m < MROWS) g_T[m * 512 + nc] = v.x;
            if (m + 1 < MROWS) g_T[(m + 1) * 512 + nc] = v.y;
        }
    }
#undef AS_T
#undef BS_T
}

// ----------------------------------------------------------------------------
// score_kernel: S[i,j] = T[b,i,:].nve[b,j,:] for 16 i-rows, j in [0,65);
// softmax + threshold -> raw masks. Grid (4, BB) = 128 blocks. (R15 version.)
// ----------------------------------------------------------------------------
__global__ __launch_bounds__(256) void score_kernel(const float* __restrict__ nve) {
    __shared__ __align__(16) float As[2][16][18];
    __shared__ __align__(16) float Bs[2][16][68];
    __shared__ float sS[16][68];
    __shared__ float su1[16];
    __shared__ float su2[65];

    const int b = blockIdx.y;
    const int i0 = 1 + 16 * blockIdx.x;
    const int tid = threadIdx.x;
    const int tm = tid & 7;
    const int tn = tid >> 3;

    if (tid < 16) su1[tid] = g_u1[b * 65 + i0 + tid];
    else if (tid < 16 + 65) su2[tid - 16] = g_u2[b * 65 + (tid - 16)];

    const float* Tb = g_T + ((size_t)b * 65 + i0) * 512;
    const float* Nb = nve + (size_t)b * 65 * 512;

    unsigned long long acc[2] = {0ull, 0ull};
    unsigned long long acc64 = 0ull;

    const int arow = tid >> 2, ak4 = (tid & 3) * 4;
    const int brow1 = (tid + 256) >> 2, bk41 = ((tid + 256) & 3) * 4;
    const bool hasB1 = (tid + 256) < 260;
    float4 ra4, rb4[2];
    {
        if (tid < 64) ra4 = *reinterpret_cast<const float4*>(&Tb[arow * 512 + ak4]);
        rb4[0] = *reinterpret_cast<const float4*>(&Nb[arow * 512 + ak4]);
        if (hasB1) rb4[1] = *reinterpret_cast<const float4*>(&Nb[brow1 * 512 + bk41]);
        if (tid < 64) {
            As[0][ak4 + 0][arow] = ra4.x;
            As[0][ak4 + 1][arow] = ra4.y;
            As[0][ak4 + 2][arow] = ra4.z;
            As[0][ak4 + 3][arow] = ra4.w;
        }
        Bs[0][ak4 + 0][arow] = rb4[0].x;
        Bs[0][ak4 + 1][arow] = rb4[0].y;
        Bs[0][ak4 + 2][arow] = rb4[0].z;
        Bs[0][ak4 + 3][arow] = rb4[0].w;
        if (hasB1) {
            Bs[0][bk41 + 0][brow1] = rb4[1].x;
            Bs[0][bk41 + 1][brow1] = rb4[1].y;
            Bs[0][bk41 + 2][brow1] = rb4[1].z;
            Bs[0][bk41 + 3][brow1] = rb4[1].w;
        }
    }
    __syncthreads();

    for (int kt = 0; kt < 32; kt++) {
        const int cur = kt & 1, nxt = cur ^ 1;
        if (kt < 31) {
            int k0 = (kt + 1) * 16;
            if (tid < 64) ra4 = *reinterpret_cast<const float4*>(&Tb[arow * 512 + k0 + ak4]);
            rb4[0] = *reinterpret_cast<const float4*>(&Nb[arow * 512 + k0 + ak4]);
            if (hasB1) rb4[1] = *reinterpret_cast<const float4*>(&Nb[brow1 * 512 + k0 + bk41]);
        }
#pragma unroll
        for (int k = 0; k < 16; k++) {
            unsigned long long a = *reinterpret_cast<const unsigned long long*>(&As[cur][k][2 * tm]);
            float2 bv = *reinterpret_cast<const float2*>(&Bs[cur][k][2 * tn]);
            fma2(acc[0], a, bcast2(bv.x));
            fma2(acc[1], a, bcast2(bv.y));
            if (tn == 0) fma2(acc64, a, bcast2(Bs[cur][k][64]));
        }
        if (kt < 31) {
            if (tid < 64) {
                As[nxt][ak4 + 0][arow] = ra4.x;
                As[nxt][ak4 + 1][arow] = ra4.y;
                As[nxt][ak4 + 2][arow] = ra4.z;
                As[nxt][ak4 + 3][arow] = ra4.w;
            }
            Bs[nxt][ak4 + 0][arow] = rb4[0].x;
            Bs[nxt][ak4 + 1][arow] = rb4[0].y;
            Bs[nxt][ak4 + 2][arow] = rb4[0].z;
            Bs[nxt][ak4 + 3][arow] = rb4[0].w;
            if (hasB1) {
                Bs[nxt][bk41 + 0][brow1] = rb4[1].x;
                Bs[nxt][bk41 + 1][brow1] = rb4[1].y;
                Bs[nxt][bk41 + 2][brow1] = rb4[1].z;
                Bs[nxt][bk41 + 3][brow1] = rb4[1].w;
            }
            __syncthreads();
        }
    }

#pragma unroll
    for (int q = 0; q < 2; q++) {
        float2 v = unpk2(acc[q]);
        sS[2 * tm][2 * tn + q] = v.x;
        sS[2 * tm + 1][2 * tn + q] = v.y;
    }
    if (tn == 0) {
        float2 v = unpk2(acc64);
        sS[2 * tm][64] = v.x;
        sS[2 * tm + 1][64] = v.y;
    }
    __syncthreads();

    const int w = tid >> 5, lane = tid & 31;
    const unsigned FULL = 0xffffffffu;
    const float INV_SQRTD = 0.044194173824159216f;
    const float s0 = g_s0;
#pragma unroll
    for (int rr = 0; rr < 2; rr++) {
        int r = w * 2 + rr;
        int i = i0 + r;
        float base = su1[r] + s0;
        int j1 = 32 + lane;
        float L0 = (lane == i) ? 0.f : (sS[r][lane] + base + su2[lane]) * INV_SQRTD;
        float L1 = (j1 == i) ? 0.f : (sS[r][j1] + base + su2[j1]) * INV_SQRTD;
        float L2 = (lane == 0)
                       ? ((i == 64) ? 0.f : (sS[r][64] + base + su2[64]) * INV_SQRTD)
                       : -1e30f;
        float mx = fmaxf(L0, fmaxf(L1, L2));
        for (int o = 16; o; o >>= 1) mx = fmaxf(mx, __shfl_xor_sync(FULL, mx, o));
        float e0 = expf(L0 - mx);
        float e1 = expf(L1 - mx);
        float e2 = (lane == 0) ? expf(L2 - mx) : 0.f;
        float sm = e0 + e1 + e2;
        for (int o = 16; o; o >>= 1) sm += __shfl_xor_sync(FULL, sm, o);
        float inv = 1.0f / sm;
        unsigned bal0 = __ballot_sync(FULL, (lane >= 1) && (e0 * inv > 0.05f));
        unsigned bal1 = __ballot_sync(FULL, e1 * inv > 0.05f);
        unsigned bal2 = __ballot_sync(FULL, (lane == 0) && (e2 * inv > 0.05f));
        if (lane == 0) {
            unsigned long long m = ((unsigned long long)(bal0 >> 1)) |
                                   ((unsigned long long)bal1 << 31) |
                                   ((unsigned long long)(bal2 & 1u) << 63);
            m |= 1ull << (i - 1);
            g_rawmask[b * 64 + (i - 1)] = m;
        }
    }
}

// ----------------------------------------------------------------------------
// cluster: greedy sequential clustering per batch + leader/member outputs
// ----------------------------------------------------------------------------
__global__ __launch_bounds__(256) void cluster_kernel(float* __restrict__ out) {
    __shared__ unsigned long long sm[64];
    __shared__ unsigned long long sf[64];
    __shared__ unsigned long long sl;
    const int b = blockIdx.x;
    const int tid = threadIdx.x;
    if (tid < 64) sm[tid] = g_rawmask[b * 64 + tid];
    __syncthreads();
    if (tid == 0) {
        unsigned long long used = 0ull, lead = 0ull;
        for (int i = 0; i < 64; i++) {
            unsigned long long m = sm[i];
            if (!((used >> i) & 1ull)) {
                lead |= 1ull << i;
                used |= m;
                sf[i] = m;
            } else {
                sf[i] = 0ull;
            }
        }
        sl = lead;
    }
    __syncthreads();
    unsigned long long lead = sl;
    if (tid < 64) {
        out[LEADER_OFF + (size_t)b * 64 + tid] = ((lead >> tid) & 1ull) ? 1.0f : 0.0f;
        g_mmask[b * 64 + tid] = sf[tid];
    }
    for (int idx = tid; idx < 4096; idx += 256) {
        out[MEMBER_OFF + (size_t)b * 4096 + idx] =
            ((sf[idx >> 6] >> (idx & 63)) & 1ull) ? 1.0f : 0.0f;
    }
}

// ----------------------------------------------------------------------------
// expansion: write-bandwidth bound (~273 MB), streaming stores.
// ----------------------------------------------------------------------------
__global__ __launch_bounds__(256) void expand_kernel(const float* __restrict__ nve,
                                                     const float* __restrict__ cls,
                                                     float* __restrict__ out) {
    const int bi = blockIdx.x;
    const int b = bi >> 6;
    const unsigned long long mask = g_mmask[bi];
    const bool lead = (mask != 0ull);

    const float4* nve4 = reinterpret_cast<const float4*>(nve);
    const float4* cls4 = reinterpret_cast<const float4*>(cls);
    float4* out4 = reinterpret_cast<float4*>(out) + (size_t)bi * 65 * 128;

    const int quad = threadIdx.x & 127;
    const int sub = threadIdx.x >> 7;
    const float4 zero4 = make_float4(0.f, 0.f, 0.f, 0.f);

    for (int r = sub; r < 65; r += 2) {
        float4 v;
        if (r == 0) {
            v = lead ? cls4[quad] : zero4;
        } else {
            v = ((mask >> (r - 1)) & 1ull) ? nve4[((size_t)b * 65 + r) * 128 + quad]
                                           : zero4;
        }
        __stcs(&out4[(size_t)r * 128 + quad], v);
    }
}

// ----------------------------------------------------------------------------
extern "C" void kernel_launch(void* const* d_in, const int* in_sizes, int n_in,
                              void* d_out, int out_size) {
    // inputs: desc_embeddings, name_value_embeddings, Wq, bq, Wk, bk, cls
    const float* nve = (const float*)d_in[1];
    const float* Wq  = (const float*)d_in[2];
    const float* bq  = (const float*)d_in[3];
    const float* Wk  = (const float*)d_in[4];
    const float* bk  = (const float*)d_in[5];
    const float* cls = (const float*)d_in[6];
    float* out = (float*)d_out;

    cudaFuncSetAttribute(gemm_T_kernel, cudaFuncAttributeMaxDynamicSharedMemorySize,
                         GT_SMEM);

    stage1_kernel<<<288, 128>>>(Wq, bq, Wk, bk);
    stage2_kernel<<<648, 128>>>(nve);
    gemm_T_kernel<<<dim3(17, 8), 128, GT_SMEM>>>(nve);
    score_kernel<<<dim3(4, BB), 256>>>(nve);
    cluster_kernel<<<BB, 256>>>(out);
    expand_kernel<<<BB * SS, 256>>>(nve, cls, out);
}